// round 1
// baseline (speedup 1.0000x reference)
#include <cuda_runtime.h>
#include <math.h>

#define N_NODES 100000
#define N_EDGES 1600000
#define SD 5
#define MAX_ITER 50

// ---- device scratch (static allocation only; no cudaMalloc allowed) ----
__device__ float g_state[N_NODES * SD];
__device__ float g_old[N_NODES * SD];
__device__ float g_acc[N_NODES * SD];
// pre1[j][e] = b1[j] + sum_i edge_feat[e][i] * W1[i][j]  (i<8), SoA for coalescing
__device__ float g_pre1[15 * N_EDGES];
__device__ int g_flag;    // any(dist > thresh) from latest node pass
__device__ int g_k;       // iteration count (num)
__device__ int g_active;  // gate decision for the current iteration

// tanh via hw exp: abs error ~1e-6, fine vs 1e-3 tolerance
__device__ __forceinline__ float fast_tanh(float x) {
    float e2 = __expf(2.0f * x);              // -> inf for large x: result 1.0 (correct)
    return 1.0f - __fdividef(2.0f, e2 + 1.0f); // -> -1.0 for very negative x (correct)
}

__global__ void setup_k() { g_flag = 0; g_k = 0; g_active = 0; }

__global__ void init_nodes_k(const float* __restrict__ st0,
                             const float* __restrict__ old0) {
    int n = blockIdx.x * blockDim.x + threadIdx.x;
    if (n >= N_NODES) return;
    float ss = 0.f;
#pragma unroll
    for (int i = 0; i < SD; i++) {
        float s = st0[n * SD + i];
        float o = old0[n * SD + i];
        g_state[n * SD + i] = s;
        g_old[n * SD + i] = o;
        g_acc[n * SD + i] = 0.f;
        float d = s - o;
        ss += d * d;
    }
    if (sqrtf(ss + 1e-11f) > 0.01f) g_flag = 1;
}

// Precompute iteration-invariant part of layer 1: edge_feat @ W1[0:8] + b1
__global__ void pre_k(const float* __restrict__ ef,
                      const float* __restrict__ W1,
                      const float* __restrict__ b1) {
    __shared__ float sW[8 * 15];
    __shared__ float sb[15];
    int t = threadIdx.x;
    if (t < 120) sW[t] = W1[t];
    if (t < 15) sb[t] = b1[t];
    __syncthreads();
    int e = blockIdx.x * blockDim.x + t;
    if (e >= N_EDGES) return;
    float4 a = *(const float4*)(ef + (size_t)e * 8);
    float4 b = *(const float4*)(ef + (size_t)e * 8 + 4);
    float f[8] = {a.x, a.y, a.z, a.w, b.x, b.y, b.z, b.w};
#pragma unroll
    for (int j = 0; j < 15; j++) {
        float h = sb[j];
#pragma unroll
        for (int i = 0; i < 8; i++) h += f[i] * sW[i * 15 + j];
        g_pre1[(size_t)j * N_EDGES + e] = h;  // SoA, coalesced
    }
}

// gate: decide whether this scan step is "live"
__global__ void gate_k() {
    int act = (g_flag != 0) && (g_k < MAX_ITER);
    g_active = act;
    if (act) g_k++;
    g_flag = 0;  // reset for the node pass of this iteration
}

// per-edge MLP + weighted scatter-add
__global__ void edge_k(const int* __restrict__ src,
                       const int* __restrict__ rows,
                       const float* __restrict__ avals,
                       const float* __restrict__ W1,
                       const float* __restrict__ W2,
                       const float* __restrict__ b2) {
    if (!g_active) return;  // frozen: no-op (uniform across grid)
    __shared__ float sG[5 * 15];   // W1 rows 8..12 (gather part)
    __shared__ float sW2[15 * 5];
    __shared__ float sb2[5];
    int t = threadIdx.x;
    if (t < 75) sG[t] = W1[120 + t];
    else if (t < 150) sW2[t - 75] = W2[t - 75];
    else if (t < 155) sb2[t - 150] = b2[t - 150];
    __syncthreads();

    int e = blockIdx.x * blockDim.x + t;
    if (e >= N_EDGES) return;

    int s = src[e];
    float g0 = g_state[s * 5 + 0];
    float g1 = g_state[s * 5 + 1];
    float g2 = g_state[s * 5 + 2];
    float g3 = g_state[s * 5 + 3];
    float g4 = g_state[s * 5 + 4];

    float h1[15];
#pragma unroll
    for (int j = 0; j < 15; j++) {
        float h = g_pre1[(size_t)j * N_EDGES + e];
        h += g0 * sG[j];
        h += g1 * sG[15 + j];
        h += g2 * sG[30 + j];
        h += g3 * sG[45 + j];
        h += g4 * sG[60 + j];
        h1[j] = fast_tanh(h);
    }

    float av = avals[e];
    int r = rows[e];
#pragma unroll
    for (int k = 0; k < 5; k++) {
        float acc = sb2[k];
#pragma unroll
        for (int j = 0; j < 15; j++) acc += h1[j] * sW2[j * 5 + k];
        atomicAdd(&g_acc[r * 5 + k], fast_tanh(acc) * av);
    }
}

// commit (if live), convergence test for next step, zero accumulator
__global__ void node_k() {
    int n = blockIdx.x * blockDim.x + threadIdx.x;
    if (n >= N_NODES) return;
    bool act = (g_active != 0);
    float s[SD], o[SD];
#pragma unroll
    for (int i = 0; i < SD; i++) {
        float scur = g_state[n * SD + i];
        if (act) {
            float a = g_acc[n * SD + i];
            g_state[n * SD + i] = a;
            g_old[n * SD + i] = scur;
            g_acc[n * SD + i] = 0.f;
            s[i] = a;
            o[i] = scur;
        } else {
            s[i] = scur;
            o[i] = g_old[n * SD + i];
        }
    }
    float ss = 0.f;
#pragma unroll
    for (int i = 0; i < SD; i++) {
        float d = s[i] - o[i];
        ss += d * d;
    }
    if (sqrtf(ss + 1e-11f) > 0.01f) g_flag = 1;
}

// readout: tanh(state @ W3 + b3) @ W4 + b4 -> softmax
__global__ void final_k(const float* __restrict__ W3,
                        const float* __restrict__ b3,
                        const float* __restrict__ W4,
                        const float* __restrict__ b4,
                        float* __restrict__ out,
                        int write_num) {
    __shared__ float sW3[50], sb3[10], sW4[70], sb4[7];
    int t = threadIdx.x;
    if (t < 50) sW3[t] = W3[t];
    if (t < 10) sb3[t] = b3[t];
    if (t < 70) sW4[t] = W4[t];
    if (t < 7) sb4[t] = b4[t];
    __syncthreads();

    int n = blockIdx.x * blockDim.x + t;
    if (n == 0 && write_num) out[(size_t)N_NODES * 7] = (float)g_k;
    if (n >= N_NODES) return;

    float s[SD];
#pragma unroll
    for (int i = 0; i < SD; i++) s[i] = g_state[n * SD + i];

    float h[10];
#pragma unroll
    for (int j = 0; j < 10; j++) {
        float a = 0.f;
#pragma unroll
        for (int i = 0; i < SD; i++) a += s[i] * sW3[i * 10 + j];
        h[j] = tanhf(a + sb3[j]);  // precise
    }

    float l[7];
    float m = -1e30f;
#pragma unroll
    for (int c = 0; c < 7; c++) {
        float a = 0.f;
#pragma unroll
        for (int j = 0; j < 10; j++) a += h[j] * sW4[j * 7 + c];
        a += sb4[c];
        l[c] = a;
        m = fmaxf(m, a);
    }
    float sum = 0.f;
#pragma unroll
    for (int c = 0; c < 7; c++) {
        float ev = expf(l[c] - m);  // precise
        l[c] = ev;
        sum += ev;
    }
    float inv = 1.0f / sum;
#pragma unroll
    for (int c = 0; c < 7; c++) out[(size_t)n * 7 + c] = l[c] * inv;
}

extern "C" void kernel_launch(void* const* d_in, const int* in_sizes, int n_in,
                              void* d_out, int out_size) {
    const float* edge_feat = (const float*)d_in[0];
    const int*   edge_src  = (const int*)d_in[1];
    const int*   arc_rows  = (const int*)d_in[2];
    const float* arc_vals  = (const float*)d_in[3];
    const float* st0       = (const float*)d_in[4];
    const float* old0      = (const float*)d_in[5];
    const float* W1        = (const float*)d_in[6];
    const float* b1        = (const float*)d_in[7];
    const float* W2        = (const float*)d_in[8];
    const float* b2        = (const float*)d_in[9];
    const float* W3        = (const float*)d_in[10];
    const float* b3        = (const float*)d_in[11];
    const float* W4        = (const float*)d_in[12];
    const float* b4        = (const float*)d_in[13];
    float* out = (float*)d_out;

    const int TB = 256;
    const int nodeBlocks = (N_NODES + TB - 1) / TB;
    const int edgeBlocks = (N_EDGES + TB - 1) / TB;

    setup_k<<<1, 1>>>();
    init_nodes_k<<<nodeBlocks, TB>>>(st0, old0);
    pre_k<<<edgeBlocks, TB>>>(edge_feat, W1, b1);

    for (int it = 0; it < MAX_ITER; ++it) {
        gate_k<<<1, 1>>>();
        edge_k<<<edgeBlocks, TB>>>(edge_src, arc_rows, arc_vals, W1, W2, b2);
        node_k<<<nodeBlocks, TB>>>();
    }

    final_k<<<nodeBlocks, TB>>>(W3, b3, W4, b4, out,
                                (out_size > N_NODES * 7) ? 1 : 0);
}

// round 2
// speedup vs baseline: 1.4125x; 1.4125x over previous
#include <cuda_runtime.h>
#include <math.h>

#define N_NODES 100000
#define N_EDGES 1600000
#define MAX_ITER 50
#define THRESH 0.01f

#define NBLK 148
#define NTHR 1024
#define EDGE_CHUNK ((N_EDGES + NBLK - 1) / NBLK)   // 10811
#define NODE_CHUNK ((N_NODES + NBLK - 1) / NBLK)   // 676

// ---- static device scratch (no cudaMalloc allowed) ----
__device__ float4 g_state4[N_NODES * 2];   // node state, stride 8 floats (32B)
__device__ float4 g_acc4[N_NODES * 2];     // scatter accumulator, stride 8 floats
__device__ int g_flag_arr[MAX_ITER + 2];   // per-iteration "any node unconverged" flags
__device__ unsigned g_arrive;              // global barrier counter

// tanh via hw exp: abs err ~1e-6 (safe vs 1e-3 tolerance and 0.01 threshold)
__device__ __forceinline__ float fast_tanh(float x) {
    float e2 = __expf(2.0f * x);
    return 1.0f - __fdividef(2.0f, e2 + 1.0f);
}

// software grid barrier: all 148 blocks are co-resident (1 wave)
__device__ __forceinline__ void gsync(unsigned& target) {
    __syncthreads();
    target += NBLK;
    if (threadIdx.x == 0) {
        __threadfence();
        atomicAdd(&g_arrive, 1u);
        while (((volatile unsigned*)&g_arrive)[0] < target) {}
        __threadfence();
    }
    __syncthreads();
}

__global__ void setup_k() {
    int t = threadIdx.x;
    if (t == 0) g_arrive = 0u;
    if (t < MAX_ITER + 2) g_flag_arr[t] = 0;
}

__global__ __launch_bounds__(NTHR, 1)
void gnn_persistent_k(const float* __restrict__ ef,
                      const int* __restrict__ src,
                      const int* __restrict__ rows,
                      const float* __restrict__ avals,
                      const float* __restrict__ st0,
                      const float* __restrict__ old0,
                      const float* __restrict__ W1, const float* __restrict__ b1,
                      const float* __restrict__ W2, const float* __restrict__ b2,
                      const float* __restrict__ W3, const float* __restrict__ b3,
                      const float* __restrict__ W4, const float* __restrict__ b4,
                      float* __restrict__ out, int write_num) {
    // padded smem weights for LDS.128
    __shared__ float sW1[13 * 16];   // [i][j], j padded 15->16
    __shared__ float sB1[16];
    __shared__ float sW2[15 * 8];    // [j][k], k padded 5->8
    __shared__ float sB2[8];
    __shared__ float sW3[5 * 10], sB3[10], sW4[10 * 7], sB4[7];

    const int tid = threadIdx.x;
    const int bid = blockIdx.x;

    // load + pad weights
    if (tid < 13 * 16) {
        int i = tid >> 4, j = tid & 15;
        sW1[tid] = (j < 15) ? W1[i * 15 + j] : 0.f;
    }
    if (tid >= 256 && tid < 256 + 16) { int j = tid - 256; sB1[j] = (j < 15) ? b1[j] : 0.f; }
    if (tid >= 288 && tid < 288 + 15 * 8) {
        int q = tid - 288, j = q >> 3, kk = q & 7;
        sW2[q] = (kk < 5) ? W2[j * 5 + kk] : 0.f;
    }
    if (tid >= 416 && tid < 424) { int kk = tid - 416; sB2[kk] = (kk < 5) ? b2[kk] : 0.f; }
    if (tid >= 448 && tid < 498) sW3[tid - 448] = W3[tid - 448];
    if (tid >= 512 && tid < 522) sB3[tid - 512] = b3[tid - 512];
    if (tid >= 544 && tid < 614) sW4[tid - 544] = W4[tid - 544];
    if (tid >= 640 && tid < 647) sB4[tid - 640] = b4[tid - 640];
    __syncthreads();

    unsigned bar = 0;

    // ---- node ownership + init ----
    const int n0 = bid * NODE_CHUNK;
    const int myNode = n0 + tid;
    const bool owner = (tid < NODE_CHUNK) && (myNode < N_NODES);
    float s[5], o[5];
    {
        int f = 0;
        if (owner) {
            float ss = 0.f;
#pragma unroll
            for (int i = 0; i < 5; i++) {
                s[i] = st0[myNode * 5 + i];
                o[i] = old0[myNode * 5 + i];
                float d = s[i] - o[i];
                ss += d * d;
            }
            __stcg(&g_state4[myNode * 2], make_float4(s[0], s[1], s[2], s[3]));
            __stcg(((float*)&g_state4[myNode * 2]) + 4, s[4]);
            if (sqrtf(ss + 1e-11f) > THRESH) f = 1;
        }
        int anyf = __syncthreads_or(f);
        if (tid == 0 && anyf) atomicOr(&g_flag_arr[0], 1);
    }
    gsync(bar);

    // ---- edge ownership ----
    const int e0 = bid * EDGE_CHUNK;
    const int e1 = (e0 + EDGE_CHUNK < N_EDGES) ? e0 + EDGE_CHUNK : N_EDGES;

    int k = 0;
    for (int it = 0; it < MAX_ITER; ++it) {
        if (__ldcg(&g_flag_arr[it]) == 0) break;
        k++;

        // ===== edge phase: per-edge MLP + vector reductions =====
        for (int e = e0 + tid; e < e1; e += NTHR) {
            int sn = __ldg(src + e);
            int rn = __ldg(rows + e);
            float av = __ldg(avals + e);

            float4 f0 = __ldg((const float4*)(ef + (size_t)e * 8));
            float4 f1 = __ldg((const float4*)(ef + (size_t)e * 8) + 1);
            float4 ga = __ldcg(&g_state4[sn * 2]);
            float g4v = __ldcg(((const float*)&g_state4[sn * 2]) + 4);

            float in[13] = {f0.x, f0.y, f0.z, f0.w, f1.x, f1.y, f1.z, f1.w,
                            ga.x, ga.y, ga.z, ga.w, g4v};

            // layer 1: h1 = tanh(in @ W1 + b1), j-vectorized over float4 groups
            float4 hv0 = *(const float4*)(sB1 + 0);
            float4 hv1 = *(const float4*)(sB1 + 4);
            float4 hv2 = *(const float4*)(sB1 + 8);
            float4 hv3 = *(const float4*)(sB1 + 12);
#pragma unroll
            for (int i = 0; i < 13; i++) {
                float xi = in[i];
                float4 w0 = *(const float4*)(sW1 + i * 16 + 0);
                float4 w1 = *(const float4*)(sW1 + i * 16 + 4);
                float4 w2 = *(const float4*)(sW1 + i * 16 + 8);
                float4 w3 = *(const float4*)(sW1 + i * 16 + 12);
                hv0.x += xi * w0.x; hv0.y += xi * w0.y; hv0.z += xi * w0.z; hv0.w += xi * w0.w;
                hv1.x += xi * w1.x; hv1.y += xi * w1.y; hv1.z += xi * w1.z; hv1.w += xi * w1.w;
                hv2.x += xi * w2.x; hv2.y += xi * w2.y; hv2.z += xi * w2.z; hv2.w += xi * w2.w;
                hv3.x += xi * w3.x; hv3.y += xi * w3.y; hv3.z += xi * w3.z; hv3.w += xi * w3.w;
            }
            float h1[15];
            h1[0] = fast_tanh(hv0.x); h1[1] = fast_tanh(hv0.y); h1[2] = fast_tanh(hv0.z); h1[3] = fast_tanh(hv0.w);
            h1[4] = fast_tanh(hv1.x); h1[5] = fast_tanh(hv1.y); h1[6] = fast_tanh(hv1.z); h1[7] = fast_tanh(hv1.w);
            h1[8] = fast_tanh(hv2.x); h1[9] = fast_tanh(hv2.y); h1[10] = fast_tanh(hv2.z); h1[11] = fast_tanh(hv2.w);
            h1[12] = fast_tanh(hv3.x); h1[13] = fast_tanh(hv3.y); h1[14] = fast_tanh(hv3.z);

            // layer 2: h2 = tanh(h1 @ W2 + b2), k-vectorized
            float4 a03 = *(const float4*)(sB2 + 0);
            float a4 = sB2[4];
#pragma unroll
            for (int j = 0; j < 15; j++) {
                float hj = h1[j];
                float4 w = *(const float4*)(sW2 + j * 8);
                float w4 = sW2[j * 8 + 4];
                a03.x += hj * w.x; a03.y += hj * w.y; a03.z += hj * w.z; a03.w += hj * w.w;
                a4 += hj * w4;
            }
            float v0 = fast_tanh(a03.x) * av;
            float v1 = fast_tanh(a03.y) * av;
            float v2 = fast_tanh(a03.z) * av;
            float v3 = fast_tanh(a03.w) * av;
            float v4 = fast_tanh(a4) * av;

            float* ap = (float*)&g_acc4[rn * 2];
            asm volatile("red.global.add.v4.f32 [%0], {%1,%2,%3,%4};"
                         :: "l"(ap), "f"(v0), "f"(v1), "f"(v2), "f"(v3) : "memory");
            asm volatile("red.global.add.f32 [%0], %1;"
                         :: "l"(ap + 4), "f"(v4) : "memory");
        }
        gsync(bar);

        // ===== node phase: commit, zero acc, convergence flag for next iter =====
        {
            int f = 0;
            if (owner) {
                float4 a = __ldcg(&g_acc4[myNode * 2]);
                float a4 = __ldcg(((const float*)&g_acc4[myNode * 2]) + 4);
                __stcg(&g_acc4[myNode * 2], make_float4(0.f, 0.f, 0.f, 0.f));
                __stcg(((float*)&g_acc4[myNode * 2]) + 4, 0.f);
                o[0] = s[0]; o[1] = s[1]; o[2] = s[2]; o[3] = s[3]; o[4] = s[4];
                s[0] = a.x; s[1] = a.y; s[2] = a.z; s[3] = a.w; s[4] = a4;
                __stcg(&g_state4[myNode * 2], make_float4(s[0], s[1], s[2], s[3]));
                __stcg(((float*)&g_state4[myNode * 2]) + 4, s[4]);
                float ss = 0.f;
#pragma unroll
                for (int i = 0; i < 5; i++) { float d = s[i] - o[i]; ss += d * d; }
                if (sqrtf(ss + 1e-11f) > THRESH) f = 1;
            }
            int anyf = __syncthreads_or(f);
            if (tid == 0 && anyf) atomicOr(&g_flag_arr[it + 1], 1);
        }
        gsync(bar);
    }

    // ===== readout (precise math): tanh(s@W3+b3)@W4+b4 -> softmax =====
    if (owner) {
        float h[10];
#pragma unroll
        for (int j = 0; j < 10; j++) {
            float a = sB3[j];
#pragma unroll
            for (int i = 0; i < 5; i++) a += s[i] * sW3[i * 10 + j];
            h[j] = tanhf(a);
        }
        float l[7];
        float m = -1e30f;
#pragma unroll
        for (int c = 0; c < 7; c++) {
            float a = sB4[c];
#pragma unroll
            for (int j = 0; j < 10; j++) a += h[j] * sW4[j * 7 + c];
            l[c] = a;
            m = fmaxf(m, a);
        }
        float sum = 0.f;
#pragma unroll
        for (int c = 0; c < 7; c++) { float ev = expf(l[c] - m); l[c] = ev; sum += ev; }
        float inv = 1.0f / sum;
#pragma unroll
        for (int c = 0; c < 7; c++) out[(size_t)myNode * 7 + c] = l[c] * inv;
    }
    if (bid == 0 && tid == 0 && write_num) out[(size_t)N_NODES * 7] = (float)k;
}

extern "C" void kernel_launch(void* const* d_in, const int* in_sizes, int n_in,
                              void* d_out, int out_size) {
    const float* edge_feat = (const float*)d_in[0];
    const int*   edge_src  = (const int*)d_in[1];
    const int*   arc_rows  = (const int*)d_in[2];
    const float* arc_vals  = (const float*)d_in[3];
    const float* st0       = (const float*)d_in[4];
    const float* old0      = (const float*)d_in[5];
    const float* W1        = (const float*)d_in[6];
    const float* b1        = (const float*)d_in[7];
    const float* W2        = (const float*)d_in[8];
    const float* b2        = (const float*)d_in[9];
    const float* W3        = (const float*)d_in[10];
    const float* b3        = (const float*)d_in[11];
    const float* W4        = (const float*)d_in[12];
    const float* b4        = (const float*)d_in[13];
    float* out = (float*)d_out;

    setup_k<<<1, 64>>>();
    gnn_persistent_k<<<NBLK, NTHR>>>(edge_feat, edge_src, arc_rows, arc_vals,
                                     st0, old0, W1, b1, W2, b2, W3, b3, W4, b4,
                                     out, (out_size > N_NODES * 7) ? 1 : 0);
}

// round 3
// speedup vs baseline: 2.0797x; 1.4723x over previous
#include <cuda_runtime.h>
#include <math.h>

#define N_NODES 100000
#define N_EDGES 1600000
#define MAX_ITER 50
#define THRESH 0.01f
#define CTANH 2.8853900817779268f   // 2*log2(e)

#define NBLK 148
#define NTHR 1024
#define NWARPS (NBLK * 32)                    // 4736
#define NGROUPS (N_EDGES / 32)                // 50000 (exact)
#define NODE_CHUNK ((N_NODES + NBLK - 1) / NBLK)   // 676
#define FULLM 0xffffffffu

typedef unsigned long long ull;

// ---- static device scratch ----
__device__ float4 g_state4[N_NODES * 2];   // node state, stride 8 floats
__device__ float4 g_acc4[N_NODES * 2];     // scatter accumulator, stride 8 floats
__device__ int    g_flag_arr[MAX_ITER + 2];
__device__ unsigned g_arrive;

__device__ int    g_cnt[N_NODES];          // histogram / scan scratch
__device__ int    g_cur[N_NODES];          // scatter cursors
__device__ int    g_eord[N_EDGES];         // row-sorted edge order
__device__ float4 g_efp[N_EDGES * 2];      // permuted edge features (8 floats)
__device__ int    g_srcp[N_EDGES];
__device__ int    g_rowp[N_EDGES];
__device__ float  g_avp[N_EDGES];
__device__ float  g_stage[304];            // scaled-weight staging for constant copy

// ---- constants (filled by D2D memcpy each launch) ----
__constant__ float2 cW1p[13 * 8];   // scaled W1, j-paired (15 padded to 16)
__constant__ float2 cB1p[8];        // scaled b1 paired
__constant__ float  cW2s[75];       // scaled W2
__constant__ float  cB2s[5];        // scaled b2
__constant__ float  cW3[50], cB3[10], cW4[70], cB4[7];

// tanh with pre-scaled argument: z = (2*log2e)*x ; tanh(x) = 1 - 2/(1+2^z)
__device__ __forceinline__ float tanh_pre(float z) {
    float ex, r;
    asm("ex2.approx.f32 %0, %1;" : "=f"(ex) : "f"(z));
    float d = ex + 1.0f;
    asm("rcp.approx.f32 %0, %1;" : "=f"(r) : "f"(d));
    return fmaf(-2.0f, r, 1.0f);
}

__device__ __forceinline__ ull pack2(float x) {
    ull r;
    asm("mov.b64 %0, {%1, %1};" : "=l"(r) : "f"(x));
    return r;
}
__device__ __forceinline__ ull fma2(ull a, ull b, ull c) {
    ull r;
    asm("fma.rn.f32x2 %0, %1, %2, %3;" : "=l"(r) : "l"(a), "l"(b), "l"(c));
    return r;
}
__device__ __forceinline__ void unpack2(ull v, float& lo, float& hi) {
    asm("mov.b64 {%0, %1}, %2;" : "=f"(lo), "=f"(hi) : "l"(v));
}

// software grid barrier (all NBLK blocks co-resident)
__device__ __forceinline__ void gsync(unsigned& target) {
    __syncthreads();
    target += NBLK;
    if (threadIdx.x == 0) {
        __threadfence();
        atomicAdd(&g_arrive, 1u);
        while (((volatile unsigned*)&g_arrive)[0] < target) {}
        __threadfence();
    }
    __syncthreads();
}

// ===== one-time setup kernels =====
__global__ void zero_k() {
    int i = blockIdx.x * blockDim.x + threadIdx.x;
    if (i == 0) g_arrive = 0u;
    if (i < MAX_ITER + 2) g_flag_arr[i] = 0;
    for (int n = i; n < N_NODES; n += gridDim.x * blockDim.x) g_cnt[n] = 0;
}

__global__ void hist_k(const int* __restrict__ rows) {
    for (int e = blockIdx.x * blockDim.x + threadIdx.x; e < N_EDGES;
         e += gridDim.x * blockDim.x)
        atomicAdd(&g_cnt[rows[e]], 1);
}

__global__ void scan_k() {   // single block, 1024 threads
    __shared__ int spart[1024];
    const int t = threadIdx.x;
    const int CH = (N_NODES + 1023) / 1024;   // 98
    int base = t * CH;
    int end = base + CH; if (end > N_NODES) end = N_NODES;
    int s = 0;
    for (int i = base; i < end; i++) s += g_cnt[i];
    spart[t] = s;
    __syncthreads();
    for (int d = 1; d < 1024; d <<= 1) {
        int v = 0;
        if (t >= d) v = spart[t - d];
        __syncthreads();
        spart[t] += v;
        __syncthreads();
    }
    int run = (t == 0) ? 0 : spart[t - 1];
    for (int i = base; i < end; i++) {
        g_cur[i] = run;
        run += g_cnt[i];
    }
}

__global__ void scatter_k(const int* __restrict__ rows) {
    for (int e = blockIdx.x * blockDim.x + threadIdx.x; e < N_EDGES;
         e += gridDim.x * blockDim.x) {
        int r = rows[e];
        int p = atomicAdd(&g_cur[r], 1);
        g_eord[p] = e;
    }
}

__global__ void permute_k(const float* __restrict__ ef,
                          const int* __restrict__ src,
                          const int* __restrict__ rows,
                          const float* __restrict__ avals) {
    const float4* ef4 = (const float4*)ef;
    for (int i = blockIdx.x * blockDim.x + threadIdx.x; i < N_EDGES;
         i += gridDim.x * blockDim.x) {
        int e = g_eord[i];
        g_efp[i * 2]     = ef4[e * 2];
        g_efp[i * 2 + 1] = ef4[e * 2 + 1];
        g_srcp[i] = src[e];
        g_rowp[i] = rows[e];
        g_avp[i]  = avals[e];
    }
}

// scale W1,b1,W2,b2 by CTANH; W1/b1 in j-paired padded layout
__global__ void scale_k(const float* __restrict__ W1, const float* __restrict__ b1,
                        const float* __restrict__ W2, const float* __restrict__ b2) {
    int t = threadIdx.x;
    for (int p = t; p < 104; p += blockDim.x) {   // W1 pairs
        int i = p >> 3, jp = p & 7;
        int j0 = jp * 2, j1 = j0 + 1;
        g_stage[p * 2]     = W1[i * 15 + j0] * CTANH;
        g_stage[p * 2 + 1] = (j1 < 15) ? W1[i * 15 + j1] * CTANH : 0.f;
    }
    if (t < 8) {                                   // b1 pairs
        int j0 = t * 2, j1 = j0 + 1;
        g_stage[208 + t * 2]     = b1[j0] * CTANH;
        g_stage[208 + t * 2 + 1] = (j1 < 15) ? b1[j1] * CTANH : 0.f;
    }
    for (int q = t; q < 75; q += blockDim.x) g_stage[224 + q] = W2[q] * CTANH;
    if (t >= 32 && t < 37) g_stage[299 + (t - 32)] = b2[t - 32] * CTANH;
}

// ===== persistent main kernel =====
__global__ __launch_bounds__(NTHR, 1)
void gnn_persistent_k(const float* __restrict__ st0,
                      const float* __restrict__ old0,
                      float* __restrict__ out, int write_num) {
    const int tid = threadIdx.x;
    const int bid = blockIdx.x;
    const int lane = tid & 31;
    const int gw = bid * 32 + (tid >> 5);

    unsigned bar = 0;

    // ---- node ownership + init ----
    const int myNode = bid * NODE_CHUNK + tid;
    const bool owner = (tid < NODE_CHUNK) && (myNode < N_NODES);
    float s[5], o[5];
    {
        int f = 0;
        if (owner) {
            float ss = 0.f;
#pragma unroll
            for (int i = 0; i < 5; i++) {
                s[i] = st0[myNode * 5 + i];
                o[i] = old0[myNode * 5 + i];
                float d = s[i] - o[i];
                ss += d * d;
            }
            __stcg(&g_state4[myNode * 2], make_float4(s[0], s[1], s[2], s[3]));
            __stcg(((float*)&g_state4[myNode * 2]) + 4, s[4]);
            __stcg(&g_acc4[myNode * 2], make_float4(0.f, 0.f, 0.f, 0.f));
            __stcg(((float*)&g_acc4[myNode * 2]) + 4, 0.f);
            if (sqrtf(ss + 1e-11f) > THRESH) f = 1;
        }
        int anyf = __syncthreads_or(f);
        if (tid == 0 && anyf) atomicOr(&g_flag_arr[0], 1);
    }
    gsync(bar);

    const ull* w1u = (const ull*)cW1p;
    const ull* b1u = (const ull*)cB1p;

    int k = 0;
    for (int it = 0; it < MAX_ITER; ++it) {
        if (__ldcg(&g_flag_arr[it]) == 0) break;
        k++;

        // ===== edge phase: groups of 32 row-sorted edges per warp =====
        for (int g = gw; g < NGROUPS; g += NWARPS) {
            int e = g * 32 + lane;
            int row = g_rowp[e];
            int sn  = g_srcp[e];
            float av = g_avp[e];
            float4 f0 = __ldcg(&g_efp[e * 2]);
            float4 f1 = __ldcg(&g_efp[e * 2 + 1]);
            float4 ga = __ldcg(&g_state4[sn * 2]);
            float g4v = __ldcg(((const float*)&g_state4[sn * 2]) + 4);

            float in[13] = {f0.x, f0.y, f0.z, f0.w, f1.x, f1.y, f1.z, f1.w,
                            ga.x, ga.y, ga.z, ga.w, g4v};

            // layer 1: packed f32x2 FMA, weights pre-scaled by 2*log2e
            ull acc[8];
#pragma unroll
            for (int p = 0; p < 8; p++) acc[p] = b1u[p];
#pragma unroll
            for (int i = 0; i < 13; i++) {
                ull x2 = pack2(in[i]);
#pragma unroll
                for (int p = 0; p < 8; p++)
                    acc[p] = fma2(x2, w1u[i * 8 + p], acc[p]);
            }
            float h1[16];
#pragma unroll
            for (int p = 0; p < 8; p++) unpack2(acc[p], h1[2 * p], h1[2 * p + 1]);
#pragma unroll
            for (int j = 0; j < 15; j++) h1[j] = tanh_pre(h1[j]);

            // layer 2 (scaled weights) + tanh + arc weight
            float z0 = cB2s[0], z1 = cB2s[1], z2 = cB2s[2], z3 = cB2s[3], z4 = cB2s[4];
#pragma unroll
            for (int j = 0; j < 15; j++) {
                float hj = h1[j];
                z0 += hj * cW2s[j * 5 + 0];
                z1 += hj * cW2s[j * 5 + 1];
                z2 += hj * cW2s[j * 5 + 2];
                z3 += hj * cW2s[j * 5 + 3];
                z4 += hj * cW2s[j * 5 + 4];
            }
            float v0 = tanh_pre(z0) * av;
            float v1 = tanh_pre(z1) * av;
            float v2 = tanh_pre(z2) * av;
            float v3 = tanh_pre(z3) * av;
            float v4 = tanh_pre(z4) * av;

            // warp segmented reduction over sorted rows
            int prev = __shfl_up_sync(FULLM, row, 1);
            bool head = (lane == 0) || (row != prev);
            unsigned hm = __ballot_sync(FULLM, head);
            unsigned below = hm & (FULLM >> (31 - lane));
            int segoff = lane - (31 - __clz(below));
#pragma unroll
            for (int d = 1; d < 32; d <<= 1) {
                float t0 = __shfl_up_sync(FULLM, v0, d);
                float t1 = __shfl_up_sync(FULLM, v1, d);
                float t2 = __shfl_up_sync(FULLM, v2, d);
                float t3 = __shfl_up_sync(FULLM, v3, d);
                float t4 = __shfl_up_sync(FULLM, v4, d);
                if (segoff >= d) { v0 += t0; v1 += t1; v2 += t2; v3 += t3; v4 += t4; }
            }
            bool tail = (lane == 31) || ((hm >> (lane + 1)) & 1u);
            if (tail) {
                float* ap = (float*)&g_acc4[row * 2];
                asm volatile("red.global.add.v4.f32 [%0], {%1,%2,%3,%4};"
                             :: "l"(ap), "f"(v0), "f"(v1), "f"(v2), "f"(v3) : "memory");
                asm volatile("red.global.add.f32 [%0], %1;"
                             :: "l"(ap + 4), "f"(v4) : "memory");
            }
        }
        gsync(bar);

        // ===== node phase: commit, zero acc, convergence flag =====
        {
            int f = 0;
            if (owner) {
                float4 a = __ldcg(&g_acc4[myNode * 2]);
                float a4 = __ldcg(((const float*)&g_acc4[myNode * 2]) + 4);
                __stcg(&g_acc4[myNode * 2], make_float4(0.f, 0.f, 0.f, 0.f));
                __stcg(((float*)&g_acc4[myNode * 2]) + 4, 0.f);
                o[0] = s[0]; o[1] = s[1]; o[2] = s[2]; o[3] = s[3]; o[4] = s[4];
                s[0] = a.x; s[1] = a.y; s[2] = a.z; s[3] = a.w; s[4] = a4;
                __stcg(&g_state4[myNode * 2], make_float4(s[0], s[1], s[2], s[3]));
                __stcg(((float*)&g_state4[myNode * 2]) + 4, s[4]);
                float ss = 0.f;
#pragma unroll
                for (int i = 0; i < 5; i++) { float d = s[i] - o[i]; ss += d * d; }
                if (sqrtf(ss + 1e-11f) > THRESH) f = 1;
            }
            int anyf = __syncthreads_or(f);
            if (tid == 0 && anyf) atomicOr(&g_flag_arr[it + 1], 1);
        }
        gsync(bar);
    }

    // ===== readout (precise math) =====
    if (owner) {
        float h[10];
#pragma unroll
        for (int j = 0; j < 10; j++) {
            float a = cB3[j];
#pragma unroll
            for (int i = 0; i < 5; i++) a += s[i] * cW3[i * 10 + j];
            h[j] = tanhf(a);
        }
        float l[7];
        float m = -1e30f;
#pragma unroll
        for (int c = 0; c < 7; c++) {
            float a = cB4[c];
#pragma unroll
            for (int j = 0; j < 10; j++) a += h[j] * cW4[j * 7 + c];
            l[c] = a;
            m = fmaxf(m, a);
        }
        float sum = 0.f;
#pragma unroll
        for (int c = 0; c < 7; c++) { float ev = expf(l[c] - m); l[c] = ev; sum += ev; }
        float inv = 1.0f / sum;
#pragma unroll
        for (int c = 0; c < 7; c++) out[(size_t)myNode * 7 + c] = l[c] * inv;
    }
    if (bid == 0 && tid == 0 && write_num) out[(size_t)N_NODES * 7] = (float)k;
}

extern "C" void kernel_launch(void* const* d_in, const int* in_sizes, int n_in,
                              void* d_out, int out_size) {
    const float* edge_feat = (const float*)d_in[0];
    const int*   edge_src  = (const int*)d_in[1];
    const int*   arc_rows  = (const int*)d_in[2];
    const float* arc_vals  = (const float*)d_in[3];
    const float* st0       = (const float*)d_in[4];
    const float* old0      = (const float*)d_in[5];
    const float* W1        = (const float*)d_in[6];
    const float* b1        = (const float*)d_in[7];
    const float* W2        = (const float*)d_in[8];
    const float* b2        = (const float*)d_in[9];
    const float* W3        = (const float*)d_in[10];
    const float* b3        = (const float*)d_in[11];
    const float* W4        = (const float*)d_in[12];
    const float* b4        = (const float*)d_in[13];
    float* out = (float*)d_out;

    // one-time permutation build + weight staging (all on stream 0, ordered)
    zero_k<<<128, 1024>>>();
    hist_k<<<256, 512>>>(arc_rows);
    scan_k<<<1, 1024>>>();
    scatter_k<<<256, 512>>>(arc_rows);
    permute_k<<<512, 256>>>(edge_feat, edge_src, arc_rows, arc_vals);
    scale_k<<<1, 128>>>(W1, b1, W2, b2);

    // copy (scaled) weights into constant memory via plain D2D memcpys
    void *pW1p, *pB1p, *pW2s, *pB2s, *pW3, *pB3, *pW4, *pB4, *pStage;
    cudaGetSymbolAddress(&pW1p, cW1p);
    cudaGetSymbolAddress(&pB1p, cB1p);
    cudaGetSymbolAddress(&pW2s, cW2s);
    cudaGetSymbolAddress(&pB2s, cB2s);
    cudaGetSymbolAddress(&pW3, cW3);
    cudaGetSymbolAddress(&pB3, cB3);
    cudaGetSymbolAddress(&pW4, cW4);
    cudaGetSymbolAddress(&pB4, cB4);
    cudaGetSymbolAddress(&pStage, g_stage);
    const float* stage = (const float*)pStage;
    cudaMemcpyAsync(pW1p, stage,       208 * 4, cudaMemcpyDeviceToDevice, 0);
    cudaMemcpyAsync(pB1p, stage + 208,  16 * 4, cudaMemcpyDeviceToDevice, 0);
    cudaMemcpyAsync(pW2s, stage + 224,  75 * 4, cudaMemcpyDeviceToDevice, 0);
    cudaMemcpyAsync(pB2s, stage + 299,   5 * 4, cudaMemcpyDeviceToDevice, 0);
    cudaMemcpyAsync(pW3, W3, 50 * 4, cudaMemcpyDeviceToDevice, 0);
    cudaMemcpyAsync(pB3, b3, 10 * 4, cudaMemcpyDeviceToDevice, 0);
    cudaMemcpyAsync(pW4, W4, 70 * 4, cudaMemcpyDeviceToDevice, 0);
    cudaMemcpyAsync(pB4, b4,  7 * 4, cudaMemcpyDeviceToDevice, 0);

    gnn_persistent_k<<<NBLK, NTHR>>>(st0, old0, out,
                                     (out_size > N_NODES * 7) ? 1 : 0);
}

// round 4
// speedup vs baseline: 2.0816x; 1.0009x over previous
#include <cuda_runtime.h>
#include <math.h>

#define N_NODES 100000
#define N_EDGES 1600000
#define MAX_ITER 50
#define THRESH 0.01f
#define CTANH 2.8853900817779268f   // 2*log2(e)

#define NBLK 148
#define NTHR 1024
#define NWARPS (NBLK * 32)                    // 4736
#define NGROUPS (N_EDGES / 32)                // 50000 (exact)
#define NODE_CHUNK ((N_NODES + NBLK - 1) / NBLK)   // 676
#define FULLM 0xffffffffu

typedef unsigned long long ull;

// ---- static device scratch ----
__device__ float4 g_state4[N_NODES * 2];
__device__ float4 g_acc4[N_NODES * 2];
__device__ int    g_flag_arr[MAX_ITER + 2];
__device__ unsigned g_arrive;

__device__ int    g_cnt[N_NODES];
__device__ int    g_cur[N_NODES];
__device__ int    g_eord[N_EDGES];
__device__ float4 g_efp[N_EDGES * 2];
__device__ int    g_srcp[N_EDGES];
__device__ int    g_rowp[N_EDGES];
__device__ float  g_avp[N_EDGES];
__device__ unsigned char g_meta[N_EDGES];   // segoff(5b) | tail(bit5)
__device__ float  g_stage[320];

// ---- constants ----
__constant__ float2 cW1p[104];   // C*W1, j-paired (15 pad 16): [i=13][jp=8]
__constant__ float2 cB1p[8];     // C*b1 paired
__constant__ float2 cW2u[40];    // [p=8][k=5]: (-2C*W2[2p][k], -2C*W2[2p+1][k] or 0)
__constant__ float  cB2f[5];     // C*(b2[k] + sum_j W2[j][k])
__constant__ float  cW3[50], cB3[10], cW4[70], cB4[7];

// r = rcp(1 + 2^z); tanh(x) = 1 - 2r when z = C*x
__device__ __forceinline__ float rtanh(float z) {
    float ex, r;
    asm("ex2.approx.f32 %0, %1;" : "=f"(ex) : "f"(z));
    float d = ex + 1.0f;
    asm("rcp.approx.f32 %0, %1;" : "=f"(r) : "f"(d));
    return r;
}
__device__ __forceinline__ ull pack2(float x) {
    ull r; asm("mov.b64 %0, {%1, %1};" : "=l"(r) : "f"(x)); return r;
}
__device__ __forceinline__ ull pack2f(float lo, float hi) {
    ull r; asm("mov.b64 %0, {%1, %2};" : "=l"(r) : "f"(lo), "f"(hi)); return r;
}
__device__ __forceinline__ ull fma2(ull a, ull b, ull c) {
    ull r; asm("fma.rn.f32x2 %0, %1, %2, %3;" : "=l"(r) : "l"(a), "l"(b), "l"(c)); return r;
}
__device__ __forceinline__ ull add2(ull a, ull b) {
    ull r; asm("add.rn.f32x2 %0, %1, %2;" : "=l"(r) : "l"(a), "l"(b)); return r;
}
__device__ __forceinline__ void unpack2(ull v, float& lo, float& hi) {
    asm("mov.b64 {%0, %1}, %2;" : "=f"(lo), "=f"(hi) : "l"(v));
}

__device__ __forceinline__ void gsync(unsigned& target) {
    __syncthreads();
    target += NBLK;
    if (threadIdx.x == 0) {
        __threadfence();
        atomicAdd(&g_arrive, 1u);
        while (((volatile unsigned*)&g_arrive)[0] < target) {}
        __threadfence();
    }
    __syncthreads();
}

// ===== setup kernels =====
__global__ void zero_k() {
    int i = blockIdx.x * blockDim.x + threadIdx.x;
    if (i == 0) g_arrive = 0u;
    if (i < MAX_ITER + 2) g_flag_arr[i] = 0;
    for (int n = i; n < N_NODES; n += gridDim.x * blockDim.x) g_cnt[n] = 0;
}

__global__ void hist_k(const int* __restrict__ rows) {
    for (int e = blockIdx.x * blockDim.x + threadIdx.x; e < N_EDGES;
         e += gridDim.x * blockDim.x)
        atomicAdd(&g_cnt[rows[e]], 1);
}

__global__ void scan_k() {
    __shared__ int spart[1024];
    const int t = threadIdx.x;
    const int CH = (N_NODES + 1023) / 1024;
    int base = t * CH;
    int end = base + CH; if (end > N_NODES) end = N_NODES;
    int s = 0;
    for (int i = base; i < end; i++) s += g_cnt[i];
    spart[t] = s;
    __syncthreads();
    for (int d = 1; d < 1024; d <<= 1) {
        int v = 0;
        if (t >= d) v = spart[t - d];
        __syncthreads();
        spart[t] += v;
        __syncthreads();
    }
    int run = (t == 0) ? 0 : spart[t - 1];
    for (int i = base; i < end; i++) { g_cur[i] = run; run += g_cnt[i]; }
}

__global__ void scatter_k(const int* __restrict__ rows) {
    for (int e = blockIdx.x * blockDim.x + threadIdx.x; e < N_EDGES;
         e += gridDim.x * blockDim.x) {
        int p = atomicAdd(&g_cur[rows[e]], 1);
        g_eord[p] = e;
    }
}

__global__ void permute_k(const float* __restrict__ ef,
                          const int* __restrict__ src,
                          const int* __restrict__ rows,
                          const float* __restrict__ avals) {
    const float4* ef4 = (const float4*)ef;
    for (int i = blockIdx.x * blockDim.x + threadIdx.x; i < N_EDGES;
         i += gridDim.x * blockDim.x) {
        int e = g_eord[i];
        g_efp[i * 2]     = ef4[e * 2];
        g_efp[i * 2 + 1] = ef4[e * 2 + 1];
        g_srcp[i] = src[e];
        g_rowp[i] = rows[e];
        g_avp[i]  = avals[e];
    }
}

// per-lane segment metadata (iteration-invariant)
__global__ void meta_k() {
    int g = blockIdx.x * (blockDim.x >> 5) + (threadIdx.x >> 5);
    if (g >= NGROUPS) return;
    int lane = threadIdx.x & 31;
    int e = g * 32 + lane;
    int row = g_rowp[e];
    int prev = __shfl_up_sync(FULLM, row, 1);
    bool head = (lane == 0) || (row != prev);
    unsigned hm = __ballot_sync(FULLM, head);
    unsigned below = hm & (FULLM >> (31 - lane));
    int segoff = lane - (31 - __clz(below));
    bool tail = (lane == 31) || ((hm >> (lane + 1)) & 1u);
    g_meta[e] = (unsigned char)(segoff | (tail ? 32 : 0));
}

// scaled/folded weight staging
__global__ void scale_k(const float* __restrict__ W1, const float* __restrict__ b1,
                        const float* __restrict__ W2, const float* __restrict__ b2) {
    int t = threadIdx.x;
    for (int p = t; p < 104; p += blockDim.x) {
        int i = p >> 3, jp = p & 7;
        int j0 = jp * 2, j1 = j0 + 1;
        g_stage[p * 2]     = W1[i * 15 + j0] * CTANH;
        g_stage[p * 2 + 1] = (j1 < 15) ? W1[i * 15 + j1] * CTANH : 0.f;
    }
    if (t < 8) {
        int j0 = t * 2, j1 = j0 + 1;
        g_stage[208 + t * 2]     = b1[j0] * CTANH;
        g_stage[208 + t * 2 + 1] = (j1 < 15) ? b1[j1] * CTANH : 0.f;
    }
    for (int q = t; q < 40; q += blockDim.x) {
        int p = q / 5, kk = q % 5;
        int j0 = 2 * p, j1 = j0 + 1;
        g_stage[224 + q * 2]     = -2.f * CTANH * W2[j0 * 5 + kk];
        g_stage[224 + q * 2 + 1] = (j1 < 15) ? -2.f * CTANH * W2[j1 * 5 + kk] : 0.f;
    }
    if (t >= 64 && t < 69) {
        int kk = t - 64;
        float s = b2[kk];
        for (int j = 0; j < 15; j++) s += W2[j * 5 + kk];
        g_stage[304 + kk] = s * CTANH;
    }
}

// ===== persistent main kernel =====
__global__ __launch_bounds__(NTHR, 1)
void gnn_persistent_k(const float* __restrict__ st0,
                      const float* __restrict__ old0,
                      float* __restrict__ out, int write_num) {
    const int tid = threadIdx.x;
    const int bid = blockIdx.x;
    const int lane = tid & 31;
    const int gw = bid * 32 + (tid >> 5);

    unsigned bar = 0;

    const int myNode = bid * NODE_CHUNK + tid;
    const bool owner = (tid < NODE_CHUNK) && (myNode < N_NODES);
    float s[5], o[5];
    {
        int f = 0;
        if (owner) {
            float ss = 0.f;
#pragma unroll
            for (int i = 0; i < 5; i++) {
                s[i] = st0[myNode * 5 + i];
                o[i] = old0[myNode * 5 + i];
                float d = s[i] - o[i];
                ss += d * d;
            }
            __stcg(&g_state4[myNode * 2], make_float4(s[0], s[1], s[2], s[3]));
            __stcg(((float*)&g_state4[myNode * 2]) + 4, s[4]);
            __stcg(&g_acc4[myNode * 2], make_float4(0.f, 0.f, 0.f, 0.f));
            __stcg(((float*)&g_acc4[myNode * 2]) + 4, 0.f);
            if (sqrtf(ss + 1e-11f) > THRESH) f = 1;
        }
        int anyf = __syncthreads_or(f);
        if (tid == 0 && anyf) atomicOr(&g_flag_arr[0], 1);
    }
    gsync(bar);

    const ull* w1u = (const ull*)cW1p;
    const ull* b1u = (const ull*)cB1p;
    const ull* w2u = (const ull*)cW2u;

    int k = 0;
    for (int it = 0; it < MAX_ITER; ++it) {
        if (__ldcg(&g_flag_arr[it]) == 0) break;
        k++;

        // ===== edge phase (software-pipelined gather) =====
        int g = gw;
        int row = 0, meta = 0;
        float av = 0.f, g4v = 0.f;
        float4 ga = make_float4(0.f, 0.f, 0.f, 0.f);
        if (g < NGROUPS) {
            int e = g * 32 + lane;
            int sn = __ldg(g_srcp + e);
            row = __ldg(g_rowp + e);
            av = __ldg(g_avp + e);
            meta = __ldg(g_meta + e);
            ga = __ldcg(&g_state4[sn * 2]);
            g4v = __ldcg(((const float*)&g_state4[sn * 2]) + 4);
        }
        while (g < NGROUPS) {
            int e = g * 32 + lane;
            int gn = g + NWARPS;

            float4 f0 = __ldg((const float4*)&g_efp[e * 2]);
            float4 f1 = __ldg((const float4*)&g_efp[e * 2 + 1]);

            // snapshot current, start prefetch of next group
            float4 cga = ga; float cg4 = g4v;
            float cav = av; int crow = row; int cmeta = meta;
            if (gn < NGROUPS) {
                int en = gn * 32 + lane;
                int sn = __ldg(g_srcp + en);
                row = __ldg(g_rowp + en);
                av = __ldg(g_avp + en);
                meta = __ldg(g_meta + en);
                ga = __ldcg(&g_state4[sn * 2]);
                g4v = __ldcg(((const float*)&g_state4[sn * 2]) + 4);
            }

            float in[13] = {f0.x, f0.y, f0.z, f0.w, f1.x, f1.y, f1.z, f1.w,
                            cga.x, cga.y, cga.z, cga.w, cg4};

            // layer 1 (packed, pre-scaled by C)
            ull acc[8];
#pragma unroll
            for (int p = 0; p < 8; p++) acc[p] = b1u[p];
#pragma unroll
            for (int i = 0; i < 13; i++) {
                ull x2 = pack2(in[i]);
#pragma unroll
                for (int p = 0; p < 8; p++)
                    acc[p] = fma2(x2, w1u[i * 8 + p], acc[p]);
            }

            // fused tanh->r + layer 2 (j-paired packed, folded constants)
            ull z[5];
#pragma unroll
            for (int kk = 0; kk < 5; kk++) z[kk] = pack2f(cB2f[kk], 0.f);
#pragma unroll
            for (int p = 0; p < 8; p++) {
                float a, b;
                unpack2(acc[p], a, b);
                float ra = rtanh(a);
                float rb = rtanh(b);   // p==7 hi is zero-padded: harmless
                ull rp = pack2f(ra, rb);
#pragma unroll
                for (int kk = 0; kk < 5; kk++)
                    z[kk] = fma2(rp, w2u[p * 5 + kk], z[kk]);
            }
            float m2av = -(cav + cav);
            float v0, v1, v2, v3, v4;
            {
                float lo, hi, r;
                unpack2(z[0], lo, hi); r = rtanh(lo + hi); v0 = fmaf(m2av, r, cav);
                unpack2(z[1], lo, hi); r = rtanh(lo + hi); v1 = fmaf(m2av, r, cav);
                unpack2(z[2], lo, hi); r = rtanh(lo + hi); v2 = fmaf(m2av, r, cav);
                unpack2(z[3], lo, hi); r = rtanh(lo + hi); v3 = fmaf(m2av, r, cav);
                unpack2(z[4], lo, hi); r = rtanh(lo + hi); v4 = fmaf(m2av, r, cav);
            }

            // segmented inclusive scan over sorted rows (packed)
            int segoff = cmeta & 31;
            ull v01 = pack2f(v0, v1);
            ull v23 = pack2f(v2, v3);
#pragma unroll
            for (int d = 1; d < 32; d <<= 1) {
                ull t01 = __shfl_up_sync(FULLM, v01, d);
                ull t23 = __shfl_up_sync(FULLM, v23, d);
                float t4 = __shfl_up_sync(FULLM, v4, d);
                if (segoff >= d) { v01 = add2(v01, t01); v23 = add2(v23, t23); v4 += t4; }
            }
            if (cmeta & 32) {
                float a0, a1, a2, a3;
                unpack2(v01, a0, a1);
                unpack2(v23, a2, a3);
                float* ap = (float*)&g_acc4[crow * 2];
                asm volatile("red.global.add.v4.f32 [%0], {%1,%2,%3,%4};"
                             :: "l"(ap), "f"(a0), "f"(a1), "f"(a2), "f"(a3) : "memory");
                asm volatile("red.global.add.f32 [%0], %1;"
                             :: "l"(ap + 4), "f"(v4) : "memory");
            }
            g = gn;
        }
        gsync(bar);

        // ===== node phase =====
        {
            int f = 0;
            if (owner) {
                float4 a = __ldcg(&g_acc4[myNode * 2]);
                float a4 = __ldcg(((const float*)&g_acc4[myNode * 2]) + 4);
                __stcg(&g_acc4[myNode * 2], make_float4(0.f, 0.f, 0.f, 0.f));
                __stcg(((float*)&g_acc4[myNode * 2]) + 4, 0.f);
                o[0] = s[0]; o[1] = s[1]; o[2] = s[2]; o[3] = s[3]; o[4] = s[4];
                s[0] = a.x; s[1] = a.y; s[2] = a.z; s[3] = a.w; s[4] = a4;
                __stcg(&g_state4[myNode * 2], make_float4(s[0], s[1], s[2], s[3]));
                __stcg(((float*)&g_state4[myNode * 2]) + 4, s[4]);
                float ss = 0.f;
#pragma unroll
                for (int i = 0; i < 5; i++) { float d = s[i] - o[i]; ss += d * d; }
                if (sqrtf(ss + 1e-11f) > THRESH) f = 1;
            }
            int anyf = __syncthreads_or(f);
            if (tid == 0 && anyf) atomicOr(&g_flag_arr[it + 1], 1);
        }
        gsync(bar);
    }

    // ===== readout (precise) =====
    if (owner) {
        float h[10];
#pragma unroll
        for (int j = 0; j < 10; j++) {
            float a = cB3[j];
#pragma unroll
            for (int i = 0; i < 5; i++) a += s[i] * cW3[i * 10 + j];
            h[j] = tanhf(a);
        }
        float l[7];
        float m = -1e30f;
#pragma unroll
        for (int c = 0; c < 7; c++) {
            float a = cB4[c];
#pragma unroll
            for (int j = 0; j < 10; j++) a += h[j] * cW4[j * 7 + c];
            l[c] = a;
            m = fmaxf(m, a);
        }
        float sum = 0.f;
#pragma unroll
        for (int c = 0; c < 7; c++) { float ev = expf(l[c] - m); l[c] = ev; sum += ev; }
        float inv = 1.0f / sum;
#pragma unroll
        for (int c = 0; c < 7; c++) out[(size_t)myNode * 7 + c] = l[c] * inv;
    }
    if (bid == 0 && tid == 0 && write_num) out[(size_t)N_NODES * 7] = (float)k;
}

extern "C" void kernel_launch(void* const* d_in, const int* in_sizes, int n_in,
                              void* d_out, int out_size) {
    const float* edge_feat = (const float*)d_in[0];
    const int*   edge_src  = (const int*)d_in[1];
    const int*   arc_rows  = (const int*)d_in[2];
    const float* arc_vals  = (const float*)d_in[3];
    const float* st0       = (const float*)d_in[4];
    const float* old0      = (const float*)d_in[5];
    const float* W1        = (const float*)d_in[6];
    const float* b1        = (const float*)d_in[7];
    const float* W2        = (const float*)d_in[8];
    const float* b2        = (const float*)d_in[9];
    const float* W3        = (const float*)d_in[10];
    const float* b3        = (const float*)d_in[11];
    const float* W4        = (const float*)d_in[12];
    const float* b4        = (const float*)d_in[13];
    float* out = (float*)d_out;

    zero_k<<<128, 1024>>>();
    hist_k<<<256, 512>>>(arc_rows);
    scan_k<<<1, 1024>>>();
    scatter_k<<<256, 512>>>(arc_rows);
    permute_k<<<512, 256>>>(edge_feat, edge_src, arc_rows, arc_vals);
    meta_k<<<(NGROUPS + 7) / 8, 256>>>();
    scale_k<<<1, 128>>>(W1, b1, W2, b2);

    void *pW1p, *pB1p, *pW2u, *pB2f, *pW3, *pB3, *pW4, *pB4, *pStage;
    cudaGetSymbolAddress(&pW1p, cW1p);
    cudaGetSymbolAddress(&pB1p, cB1p);
    cudaGetSymbolAddress(&pW2u, cW2u);
    cudaGetSymbolAddress(&pB2f, cB2f);
    cudaGetSymbolAddress(&pW3, cW3);
    cudaGetSymbolAddress(&pB3, cB3);
    cudaGetSymbolAddress(&pW4, cW4);
    cudaGetSymbolAddress(&pB4, cB4);
    cudaGetSymbolAddress(&pStage, g_stage);
    const float* stage = (const float*)pStage;
    cudaMemcpyAsync(pW1p, stage,       208 * 4, cudaMemcpyDeviceToDevice, 0);
    cudaMemcpyAsync(pB1p, stage + 208,  16 * 4, cudaMemcpyDeviceToDevice, 0);
    cudaMemcpyAsync(pW2u, stage + 224,  80 * 4, cudaMemcpyDeviceToDevice, 0);
    cudaMemcpyAsync(pB2f, stage + 304,   5 * 4, cudaMemcpyDeviceToDevice, 0);
    cudaMemcpyAsync(pW3, W3, 50 * 4, cudaMemcpyDeviceToDevice, 0);
    cudaMemcpyAsync(pB3, b3, 10 * 4, cudaMemcpyDeviceToDevice, 0);
    cudaMemcpyAsync(pW4, W4, 70 * 4, cudaMemcpyDeviceToDevice, 0);
    cudaMemcpyAsync(pB4, b4,  7 * 4, cudaMemcpyDeviceToDevice, 0);

    gnn_persistent_k<<<NBLK, NTHR>>>(st0, old0, out,
                                     (out_size > N_NODES * 7) ? 1 : 0);
}

// round 5
// speedup vs baseline: 2.2432x; 1.0776x over previous
#include <cuda_runtime.h>
#include <cuda_fp16.h>
#include <math.h>

#define N_NODES 100000
#define N_EDGES 1600000
#define MAX_ITER 50
#define THRESH 0.01f
#define CTANH 2.8853900817779268f   // 2*log2(e)

#define NBLK 148
#define NTHR 1024
#define NWARPS (NBLK * 32)                  // 4736
#define NGROUPS (N_EDGES / 32)              // 50000 exact
#define NODE_CHUNK ((N_NODES + NBLK - 1) / NBLK)   // 676
#define FULLM 0xffffffffu

typedef unsigned long long ull;

// all scaled/folded weights in one constant block (single D2D memcpy)
struct CW {
    float2 W1p[104];   // C*W1 j-paired (15 pad 16): [i=13][jp=8]
    float2 B1p[8];     // C*b1 paired
    float2 W2u[40];    // [p=8][k=5]: (-2C*W2[2p][k], -2C*W2[2p+1][k])
    float  B2f[5];     // C*(b2[k] + sum_j W2[j][k])
    float  W3[50], B3[10], W4[70], B4[7];
};
__constant__ CW cw;

// ---- static device scratch ----
__device__ unsigned g_arrive;               // zero-init, monotonic forever
__device__ uint4  g_stateh[N_NODES];        // state as fp16 x8 (5 used)
__device__ float4 g_acc4[N_NODES * 2];      // fp32 accumulator, stride 8
__device__ int    g_flag_arr[MAX_ITER + 2];
__device__ int    g_cnt[N_NODES];
__device__ int    g_cur[N_NODES];
__device__ int    g_part[NBLK];
__device__ int    g_eord[N_EDGES];
__device__ float4 g_efp[N_EDGES * 2];       // permuted edge features
__device__ int2   g_sa[N_EDGES];            // {src, av bits}
__device__ int    g_rowp[N_EDGES];          // row | segoff<<18 | tail<<23
__device__ float  g_stage[448];

// r = rcp(1 + 2^z); tanh(x) = 1 - 2r when z = C*x  (abs err ~1e-6)
__device__ __forceinline__ float rtanh(float z) {
    float ex, r;
    asm("ex2.approx.f32 %0, %1;" : "=f"(ex) : "f"(z));
    float d = ex + 1.0f;
    asm("rcp.approx.f32 %0, %1;" : "=f"(r) : "f"(d));
    return r;
}
__device__ __forceinline__ ull pack2(float x) {
    ull r; asm("mov.b64 %0, {%1, %1};" : "=l"(r) : "f"(x)); return r;
}
__device__ __forceinline__ ull pack2f(float lo, float hi) {
    ull r; asm("mov.b64 %0, {%1, %2};" : "=l"(r) : "f"(lo), "f"(hi)); return r;
}
__device__ __forceinline__ ull fma2(ull a, ull b, ull c) {
    ull r; asm("fma.rn.f32x2 %0, %1, %2, %3;" : "=l"(r) : "l"(a), "l"(b), "l"(c)); return r;
}
__device__ __forceinline__ ull add2(ull a, ull b) {
    ull r; asm("add.rn.f32x2 %0, %1, %2;" : "=l"(r) : "l"(a), "l"(b)); return r;
}
__device__ __forceinline__ void unpack2(ull v, float& lo, float& hi) {
    asm("mov.b64 {%0, %1}, %2;" : "=f"(lo), "=f"(hi) : "l"(v));
}

// self-normalizing grid barrier: monotonic counter, no reset needed ever
__device__ __forceinline__ void gsync() {
    __syncthreads();
    if (threadIdx.x == 0) {
        __threadfence();
        unsigned old = atomicAdd(&g_arrive, 1u);
        unsigned tgt = (old / NBLK + 1u) * NBLK;
        while (((volatile unsigned*)&g_arrive)[0] < tgt) {}
        __threadfence();
    }
    __syncthreads();
}

// ===== one persistent build kernel: zero -> hist -> scan -> scatter -> permute =====
__global__ __launch_bounds__(NTHR, 1)
void build_k(const float* __restrict__ ef, const int* __restrict__ src,
             const int* __restrict__ rows, const float* __restrict__ avals,
             const float* __restrict__ W1, const float* __restrict__ b1,
             const float* __restrict__ W2, const float* __restrict__ b2,
             const float* __restrict__ W3, const float* __restrict__ b3,
             const float* __restrict__ W4, const float* __restrict__ b4) {
    __shared__ int sarr[NTHR];
    __shared__ int spart[NBLK];
    const int tid = threadIdx.x, bid = blockIdx.x;
    const int gsz = NBLK * NTHR;
    const int gi = bid * NTHR + tid;

    // phase 0: zero counters/flags + stage scaled weights (block 0)
    for (int n = gi; n < N_NODES; n += gsz) g_cnt[n] = 0;
    if (gi < MAX_ITER + 2) g_flag_arr[gi] = 0;
    if (bid == 0) {
        for (int p = tid; p < 104; p += NTHR) {
            int i = p >> 3, jp = p & 7;
            int j0 = jp * 2, j1 = j0 + 1;
            g_stage[p * 2]     = W1[i * 15 + j0] * CTANH;
            g_stage[p * 2 + 1] = (j1 < 15) ? W1[i * 15 + j1] * CTANH : 0.f;
        }
        if (tid < 8) {
            int j0 = tid * 2, j1 = j0 + 1;
            g_stage[208 + tid * 2]     = b1[j0] * CTANH;
            g_stage[208 + tid * 2 + 1] = (j1 < 15) ? b1[j1] * CTANH : 0.f;
        }
        for (int q = tid; q < 40; q += NTHR) {
            int p = q / 5, kk = q % 5;
            int j0 = 2 * p, j1 = j0 + 1;
            g_stage[224 + q * 2]     = -2.f * CTANH * W2[j0 * 5 + kk];
            g_stage[224 + q * 2 + 1] = (j1 < 15) ? -2.f * CTANH * W2[j1 * 5 + kk] : 0.f;
        }
        if (tid >= 64 && tid < 69) {
            int kk = tid - 64;
            float sm = b2[kk];
            for (int j = 0; j < 15; j++) sm += W2[j * 5 + kk];
            g_stage[304 + kk] = sm * CTANH;
        }
        if (tid >= 128 && tid < 178) g_stage[309 + tid - 128] = W3[tid - 128];
        if (tid >= 192 && tid < 202) g_stage[359 + tid - 192] = b3[tid - 192];
        if (tid >= 224 && tid < 294) g_stage[369 + tid - 224] = W4[tid - 224];
        if (tid >= 320 && tid < 327) g_stage[439 + tid - 320] = b4[tid - 320];
    }
    gsync();

    // phase 1: histogram of rows
    for (int e = gi; e < N_EDGES; e += gsz) atomicAdd(&g_cnt[rows[e]], 1);
    gsync();

    // phase 2: per-block chunk scan (inclusive, in smem; smem persists)
    const int base = bid * NODE_CHUNK;
    const int nn = base + tid;
    int cv = (tid < NODE_CHUNK && nn < N_NODES) ? g_cnt[nn] : 0;
    sarr[tid] = cv;
    __syncthreads();
    for (int d = 1; d < NTHR; d <<= 1) {
        int v = (tid >= d) ? sarr[tid - d] : 0;
        __syncthreads();
        sarr[tid] += v;
        __syncthreads();
    }
    if (tid == NTHR - 1) g_part[bid] = sarr[NTHR - 1];
    gsync();

    // phase 3: block 0 exclusive-scans the 148 partials
    if (bid == 0) {
        if (tid < NBLK) spart[tid] = g_part[tid];
        __syncthreads();
        if (tid == 0) {
            int run = 0;
            for (int i = 0; i < NBLK; i++) { int t = spart[i]; spart[i] = run; run += t; }
        }
        __syncthreads();
        if (tid < NBLK) g_part[tid] = spart[tid];
    }
    gsync();

    // phase 4: write exclusive cursors
    {
        int off = g_part[bid];
        if (tid < NODE_CHUNK && nn < N_NODES) g_cur[nn] = off + sarr[tid] - cv;
    }
    gsync();

    // phase 5: scatter edge order
    for (int e = gi; e < N_EDGES; e += gsz) {
        int p = atomicAdd(&g_cur[rows[e]], 1);
        g_eord[p] = e;
    }
    gsync();

    // phase 6: permute arrays + inline segment metadata
    {
        const int lane = tid & 31;
        const int gw = bid * 32 + (tid >> 5);
        const float4* ef4 = (const float4*)ef;
        for (int g = gw; g < NGROUPS; g += NWARPS) {
            int i = g * 32 + lane;
            int e = g_eord[i];
            int r = rows[e];
            g_efp[i * 2]     = ef4[e * 2];
            g_efp[i * 2 + 1] = ef4[e * 2 + 1];
            g_sa[i] = make_int2(src[e], __float_as_int(avals[e]));
            int prev = __shfl_up_sync(FULLM, r, 1);
            bool head = (lane == 0) || (r != prev);
            unsigned hm = __ballot_sync(FULLM, head);
            unsigned below = hm & (FULLM >> (31 - lane));
            int segoff = lane - (31 - __clz(below));
            bool tail = (lane == 31) || ((hm >> (lane + 1)) & 1u);
            g_rowp[i] = r | (segoff << 18) | (tail ? (1 << 23) : 0);
        }
    }
}

// ===== persistent main kernel =====
__global__ __launch_bounds__(NTHR, 1)
void gnn_main_k(const float* __restrict__ st0,
                const float* __restrict__ old0,
                float* __restrict__ out, int write_num) {
    const int tid = threadIdx.x;
    const int bid = blockIdx.x;
    const int lane = tid & 31;
    const int gw = bid * 32 + (tid >> 5);

    const int myNode = bid * NODE_CHUNK + tid;
    const bool owner = (tid < NODE_CHUNK) && (myNode < N_NODES);
    float s[5], o[5];
    {
        int f = 0;
        if (owner) {
            float ss = 0.f;
#pragma unroll
            for (int i = 0; i < 5; i++) {
                s[i] = st0[myNode * 5 + i];
                o[i] = old0[myNode * 5 + i];
                float d = s[i] - o[i];
                ss += d * d;
            }
            __half2 p01 = __floats2half2_rn(s[0], s[1]);
            __half2 p23 = __floats2half2_rn(s[2], s[3]);
            __half2 p4  = __floats2half2_rn(s[4], 0.f);
            uint4 sv;
            sv.x = *(unsigned*)&p01; sv.y = *(unsigned*)&p23;
            sv.z = *(unsigned*)&p4;  sv.w = 0u;
            __stcg(&g_stateh[myNode], sv);
            __stcg(&g_acc4[myNode * 2], make_float4(0.f, 0.f, 0.f, 0.f));
            __stcg(((float*)&g_acc4[myNode * 2]) + 4, 0.f);
            if (sqrtf(ss + 1e-11f) > THRESH) f = 1;
        }
        int anyf = __syncthreads_or(f);
        if (tid == 0 && anyf) atomicOr(&g_flag_arr[0], 1);
    }
    gsync();

    const ull* w1u = (const ull*)cw.W1p;
    const ull* b1u = (const ull*)cw.B1p;
    const ull* w2u = (const ull*)cw.W2u;

    int k = 0;
    for (int it = 0; it < MAX_ITER; ++it) {
        if (__ldcg(&g_flag_arr[it]) == 0) break;
        k++;

        // ===== edge phase: software-pipelined =====
        int g = gw;
        int2 sa = make_int2(0, 0);
        int rp = 0;
        uint4 sv = make_uint4(0, 0, 0, 0);
        if (g < NGROUPS) {
            int e = g * 32 + lane;
            sa = __ldg(&g_sa[e]);
            rp = __ldg(&g_rowp[e]);
            sv = __ldcg(&g_stateh[sa.x]);
        }
        while (g < NGROUPS) {
            int e = g * 32 + lane;
            int gn = g + NWARPS;

            float4 f0 = __ldg((const float4*)&g_efp[e * 2]);
            float4 f1 = __ldg((const float4*)&g_efp[e * 2 + 1]);

            uint4 csv = sv;
            int crp = rp;
            float cav = __int_as_float(sa.y);
            if (gn < NGROUPS) {
                int en = gn * 32 + lane;
                sa = __ldg(&g_sa[en]);
                rp = __ldg(&g_rowp[en]);
                sv = __ldcg(&g_stateh[sa.x]);
            }

            float2 p01 = __half22float2(*(__half2*)&csv.x);
            float2 p23 = __half22float2(*(__half2*)&csv.y);
            float2 p4  = __half22float2(*(__half2*)&csv.z);

            float in[13] = {f0.x, f0.y, f0.z, f0.w, f1.x, f1.y, f1.z, f1.w,
                            p01.x, p01.y, p23.x, p23.y, p4.x};

            // layer 1 (packed, pre-scaled by C)
            ull acc[8];
#pragma unroll
            for (int p = 0; p < 8; p++) acc[p] = b1u[p];
#pragma unroll
            for (int i = 0; i < 13; i++) {
                ull x2 = pack2(in[i]);
#pragma unroll
                for (int p = 0; p < 8; p++)
                    acc[p] = fma2(x2, w1u[i * 8 + p], acc[p]);
            }

            // fused tanh->r + layer 2 (packed, folded)
            ull z[5];
#pragma unroll
            for (int kk = 0; kk < 5; kk++) z[kk] = pack2f(cw.B2f[kk], 0.f);
#pragma unroll
            for (int p = 0; p < 8; p++) {
                float a, b;
                unpack2(acc[p], a, b);
                float ra = rtanh(a);
                float rb = rtanh(b);
                ull rpk = pack2f(ra, rb);
#pragma unroll
                for (int kk = 0; kk < 5; kk++)
                    z[kk] = fma2(rpk, w2u[p * 5 + kk], z[kk]);
            }
            float m2av = -(cav + cav);
            float v0, v1, v2, v3, v4;
            {
                float lo, hi, r;
                unpack2(z[0], lo, hi); r = rtanh(lo + hi); v0 = fmaf(m2av, r, cav);
                unpack2(z[1], lo, hi); r = rtanh(lo + hi); v1 = fmaf(m2av, r, cav);
                unpack2(z[2], lo, hi); r = rtanh(lo + hi); v2 = fmaf(m2av, r, cav);
                unpack2(z[3], lo, hi); r = rtanh(lo + hi); v3 = fmaf(m2av, r, cav);
                unpack2(z[4], lo, hi); r = rtanh(lo + hi); v4 = fmaf(m2av, r, cav);
            }

            // segmented inclusive scan over sorted rows (packed)
            int segoff = (crp >> 18) & 31;
            ull v01 = pack2f(v0, v1);
            ull v23 = pack2f(v2, v3);
#pragma unroll
            for (int d = 1; d < 32; d <<= 1) {
                ull t01 = __shfl_up_sync(FULLM, v01, d);
                ull t23 = __shfl_up_sync(FULLM, v23, d);
                float t4 = __shfl_up_sync(FULLM, v4, d);
                if (segoff >= d) { v01 = add2(v01, t01); v23 = add2(v23, t23); v4 += t4; }
            }
            if (crp & (1 << 23)) {
                int crow = crp & 0x3FFFF;
                float a0, a1, a2, a3;
                unpack2(v01, a0, a1);
                unpack2(v23, a2, a3);
                float* ap = (float*)&g_acc4[crow * 2];
                asm volatile("red.global.add.v4.f32 [%0], {%1,%2,%3,%4};"
                             :: "l"(ap), "f"(a0), "f"(a1), "f"(a2), "f"(a3) : "memory");
                asm volatile("red.global.add.f32 [%0], %1;"
                             :: "l"(ap + 4), "f"(v4) : "memory");
            }
            g = gn;
        }
        gsync();

        // ===== node phase =====
        {
            int f = 0;
            if (owner) {
                float4 a = __ldcg(&g_acc4[myNode * 2]);
                float a4 = __ldcg(((const float*)&g_acc4[myNode * 2]) + 4);
                __stcg(&g_acc4[myNode * 2], make_float4(0.f, 0.f, 0.f, 0.f));
                __stcg(((float*)&g_acc4[myNode * 2]) + 4, 0.f);
                o[0] = s[0]; o[1] = s[1]; o[2] = s[2]; o[3] = s[3]; o[4] = s[4];
                s[0] = a.x; s[1] = a.y; s[2] = a.z; s[3] = a.w; s[4] = a4;
                __half2 p01 = __floats2half2_rn(s[0], s[1]);
                __half2 p23 = __floats2half2_rn(s[2], s[3]);
                __half2 p4  = __floats2half2_rn(s[4], 0.f);
                uint4 svw;
                svw.x = *(unsigned*)&p01; svw.y = *(unsigned*)&p23;
                svw.z = *(unsigned*)&p4;  svw.w = 0u;
                __stcg(&g_stateh[myNode], svw);
                float ss = 0.f;
#pragma unroll
                for (int i = 0; i < 5; i++) { float d = s[i] - o[i]; ss += d * d; }
                if (sqrtf(ss + 1e-11f) > THRESH) f = 1;
            }
            int anyf = __syncthreads_or(f);
            if (tid == 0 && anyf) atomicOr(&g_flag_arr[it + 1], 1);
        }
        gsync();
    }

    // ===== readout (precise) =====
    if (owner) {
        float h[10];
#pragma unroll
        for (int j = 0; j < 10; j++) {
            float a = cw.B3[j];
#pragma unroll
            for (int i = 0; i < 5; i++) a += s[i] * cw.W3[i * 10 + j];
            h[j] = tanhf(a);
        }
        float l[7];
        float m = -1e30f;
#pragma unroll
        for (int c = 0; c < 7; c++) {
            float a = cw.B4[c];
#pragma unroll
            for (int j = 0; j < 10; j++) a += h[j] * cw.W4[j * 7 + c];
            l[c] = a;
            m = fmaxf(m, a);
        }
        float sum = 0.f;
#pragma unroll
        for (int c = 0; c < 7; c++) { float ev = expf(l[c] - m); l[c] = ev; sum += ev; }
        float inv = 1.0f / sum;
#pragma unroll
        for (int c = 0; c < 7; c++) out[(size_t)myNode * 7 + c] = l[c] * inv;
    }
    if (bid == 0 && tid == 0 && write_num) out[(size_t)N_NODES * 7] = (float)k;
}

extern "C" void kernel_launch(void* const* d_in, const int* in_sizes, int n_in,
                              void* d_out, int out_size) {
    const float* edge_feat = (const float*)d_in[0];
    const int*   edge_src  = (const int*)d_in[1];
    const int*   arc_rows  = (const int*)d_in[2];
    const float* arc_vals  = (const float*)d_in[3];
    const float* st0       = (const float*)d_in[4];
    const float* old0      = (const float*)d_in[5];
    const float* W1        = (const float*)d_in[6];
    const float* b1        = (const float*)d_in[7];
    const float* W2        = (const float*)d_in[8];
    const float* b2        = (const float*)d_in[9];
    const float* W3        = (const float*)d_in[10];
    const float* b3        = (const float*)d_in[11];
    const float* W4        = (const float*)d_in[12];
    const float* b4        = (const float*)d_in[13];
    float* out = (float*)d_out;

    build_k<<<NBLK, NTHR>>>(edge_feat, edge_src, arc_rows, arc_vals,
                            W1, b1, W2, b2, W3, b3, W4, b4);

    void *pCW, *pStage;
    cudaGetSymbolAddress(&pCW, cw);
    cudaGetSymbolAddress(&pStage, g_stage);
    cudaMemcpyAsync(pCW, pStage, sizeof(CW), cudaMemcpyDeviceToDevice, 0);

    gnn_main_k<<<NBLK, NTHR>>>(st0, old0, out, (out_size > N_NODES * 7) ? 1 : 0);
}

// round 7
// speedup vs baseline: 2.3290x; 1.0383x over previous
#include <cuda_runtime.h>
#include <cuda_fp16.h>
#include <math.h>

#define N_NODES 100000
#define N_EDGES 1600000
#define MAX_ITER 50
#define THRESH 0.01f
#define CTANH 2.8853900817779268f   // 2*log2(e)

#define NBLK 148
#define NTHR 1024
#define NWARPS (NBLK * 32)                  // 4736
#define NGROUPS (N_EDGES / 32)              // 50000 exact
#define NODE_CHUNK ((N_NODES + NBLK - 1) / NBLK)   // 676
#define FULLM 0xffffffffu

typedef unsigned long long ull;

// all scaled/folded weights in one constant block (single D2D memcpy)
struct CW {
    float2 W1s[40];   // C*W1 rows 8..12, j-paired: [i=5][jp=8]
    float2 W2u[40];   // [p=8][k=5]: (-2C*W2[2p][k], -2C*W2[2p+1][k] or 0)
    float  B2f[5];    // C*(b2[k] + sum_j W2[j][k])
    float  W3[50], B3[10], W4[70], B4[7];
};
__constant__ CW cw;

// ---- static device scratch ----
__device__ unsigned g_arrive;               // zero-init, monotonic forever
__device__ uint4  g_stateh[N_NODES];        // state as fp16 (5 used of 8)
__device__ float4 g_acc4[N_NODES * 2];      // fp32 accumulator, stride 8
__device__ int    g_flag_arr[MAX_ITER + 2];
__device__ int    g_cnt[N_NODES];
__device__ int    g_cur[N_NODES];
__device__ int    g_part[NBLK];
__device__ int    g_eord[N_EDGES];
__device__ uint4  g_pre1h[N_EDGES * 2];     // C*(b1 + ef@W1[0:8]) fp16 j-pairs, 32B/edge
__device__ int2   g_sa[N_EDGES];            // {src, av bits}
__device__ int    g_rowp[N_EDGES];          // row | segoff<<18 | tail<<23
__device__ float  g_stage[304];

// r = rcp(1 + 2^z); tanh(x) = 1 - 2r when z = C*x  (abs err ~1e-6)
__device__ __forceinline__ float rtanh(float z) {
    float ex, r;
    asm("ex2.approx.f32 %0, %1;" : "=f"(ex) : "f"(z));
    float d = ex + 1.0f;
    asm("rcp.approx.f32 %0, %1;" : "=f"(r) : "f"(d));
    return r;
}
__device__ __forceinline__ ull pack2(float x) {
    ull r; asm("mov.b64 %0, {%1, %1};" : "=l"(r) : "f"(x)); return r;
}
__device__ __forceinline__ ull pack2f(float lo, float hi) {
    ull r; asm("mov.b64 %0, {%1, %2};" : "=l"(r) : "f"(lo), "f"(hi)); return r;
}
__device__ __forceinline__ ull fma2(ull a, ull b, ull c) {
    ull r; asm("fma.rn.f32x2 %0, %1, %2, %3;" : "=l"(r) : "l"(a), "l"(b), "l"(c)); return r;
}
__device__ __forceinline__ ull add2(ull a, ull b) {
    ull r; asm("add.rn.f32x2 %0, %1, %2;" : "=l"(r) : "l"(a), "l"(b)); return r;
}
__device__ __forceinline__ void unpack2(ull v, float& lo, float& hi) {
    asm("mov.b64 {%0, %1}, %2;" : "=f"(lo), "=f"(hi) : "l"(v));
}

// self-normalizing grid barrier: monotonic counter, no reset needed
__device__ __forceinline__ void gsync() {
    __syncthreads();
    if (threadIdx.x == 0) {
        __threadfence();
        unsigned old = atomicAdd(&g_arrive, 1u);
        unsigned tgt = (old / NBLK + 1u) * NBLK;
        while (((volatile unsigned*)&g_arrive)[0] < tgt) {}
        __threadfence();
    }
    __syncthreads();
}

// ===== one persistent build kernel =====
__global__ __launch_bounds__(NTHR, 1)
void build_k(const float* __restrict__ ef, const int* __restrict__ src,
             const int* __restrict__ rows, const float* __restrict__ avals,
             const float* __restrict__ W1, const float* __restrict__ b1,
             const float* __restrict__ W2, const float* __restrict__ b2,
             const float* __restrict__ W3, const float* __restrict__ b3,
             const float* __restrict__ W4, const float* __restrict__ b4) {
    __shared__ int sarr[NTHR];
    __shared__ int spart[NBLK];
    __shared__ float2 sW1a[64];   // C*W1 rows 0..7, j-paired [i8][jp]
    __shared__ float2 sB1a[8];    // C*b1 j-paired
    const int tid = threadIdx.x, bid = blockIdx.x;
    const int gsz = NBLK * NTHR;
    const int gi = bid * NTHR + tid;

    // phase 0: zero counters/flags, stage smem C*W1a/C*b1, stage constants
    for (int n = gi; n < N_NODES; n += gsz) g_cnt[n] = 0;
    if (gi < MAX_ITER + 2) g_flag_arr[gi] = 0;
    if (tid < 64) {
        int i8 = tid >> 3, jp = tid & 7;
        int j0 = jp * 2, j1 = j0 + 1;
        sW1a[tid] = make_float2(W1[i8 * 15 + j0] * CTANH,
                                (j1 < 15) ? W1[i8 * 15 + j1] * CTANH : 0.f);
    } else if (tid < 72) {
        int jp = tid - 64;
        int j0 = jp * 2, j1 = j0 + 1;
        sB1a[jp] = make_float2(b1[j0] * CTANH,
                               (j1 < 15) ? b1[j1] * CTANH : 0.f);
    }
    if (bid == 0) {
        for (int q = tid; q < 40; q += NTHR) {          // C*W1 rows 8..12
            int i = 8 + (q >> 3), jp = q & 7;
            int j0 = jp * 2, j1 = j0 + 1;
            g_stage[2 * q]     = W1[i * 15 + j0] * CTANH;
            g_stage[2 * q + 1] = (j1 < 15) ? W1[i * 15 + j1] * CTANH : 0.f;
        }
        for (int q = tid; q < 40; q += NTHR) {          // -2C*W2 pairs
            int p = q / 5, kk = q % 5;
            int j0 = 2 * p, j1 = j0 + 1;
            g_stage[80 + 2 * q]     = -2.f * CTANH * W2[j0 * 5 + kk];
            g_stage[80 + 2 * q + 1] = (j1 < 15) ? -2.f * CTANH * W2[j1 * 5 + kk] : 0.f;
        }
        if (tid >= 128 && tid < 133) {                  // B2f folded
            int kk = tid - 128;
            float sm = b2[kk];
            for (int j = 0; j < 15; j++) sm += W2[j * 5 + kk];
            g_stage[160 + kk] = sm * CTANH;
        }
        if (tid >= 160 && tid < 210) g_stage[165 + tid - 160] = W3[tid - 160];
        if (tid >= 224 && tid < 234) g_stage[215 + tid - 224] = b3[tid - 224];
        if (tid >= 256 && tid < 326) g_stage[225 + tid - 256] = W4[tid - 256];
        if (tid >= 352 && tid < 359) g_stage[295 + tid - 352] = b4[tid - 352];
    }
    gsync();

    // phase 1: histogram of rows
    for (int e = gi; e < N_EDGES; e += gsz) atomicAdd(&g_cnt[rows[e]], 1);
    gsync();

    // phase 2: per-block chunk scan
    const int nn = bid * NODE_CHUNK + tid;
    int cv = (tid < NODE_CHUNK && nn < N_NODES) ? g_cnt[nn] : 0;
    sarr[tid] = cv;
    __syncthreads();
    for (int d = 1; d < NTHR; d <<= 1) {
        int v = (tid >= d) ? sarr[tid - d] : 0;
        __syncthreads();
        sarr[tid] += v;
        __syncthreads();
    }
    if (tid == NTHR - 1) g_part[bid] = sarr[NTHR - 1];
    gsync();

    // phase 3: block 0 scans partials
    if (bid == 0) {
        if (tid < NBLK) spart[tid] = g_part[tid];
        __syncthreads();
        if (tid == 0) {
            int run = 0;
            for (int i = 0; i < NBLK; i++) { int t = spart[i]; spart[i] = run; run += t; }
        }
        __syncthreads();
        if (tid < NBLK) g_part[tid] = spart[tid];
    }
    gsync();

    // phase 4: exclusive cursors
    {
        int off = g_part[bid];
        if (tid < NODE_CHUNK && nn < N_NODES) g_cur[nn] = off + sarr[tid] - cv;
    }
    gsync();

    // phase 5: scatter edge order
    for (int e = gi; e < N_EDGES; e += gsz) {
        int p = atomicAdd(&g_cur[rows[e]], 1);
        g_eord[p] = e;
    }
    gsync();

    // phase 6: permute + pre1 compute (fp16 pairs, 2x uint4) + segment metadata
    {
        const int lane = tid & 31;
        const int gw = bid * 32 + (tid >> 5);
        const float4* ef4 = (const float4*)ef;
        const ull* w1a = (const ull*)sW1a;
        const ull* b1a = (const ull*)sB1a;
        for (int g = gw; g < NGROUPS; g += NWARPS) {
            int i = g * 32 + lane;
            int e = g_eord[i];
            int r = rows[e];
            float4 f0 = ef4[e * 2];
            float4 f1 = ef4[e * 2 + 1];
            float in8[8] = {f0.x, f0.y, f0.z, f0.w, f1.x, f1.y, f1.z, f1.w};
            ull acc[8];
#pragma unroll
            for (int p = 0; p < 8; p++) acc[p] = b1a[p];
#pragma unroll
            for (int i8 = 0; i8 < 8; i8++) {
                ull x2 = pack2(in8[i8]);
#pragma unroll
                for (int p = 0; p < 8; p++)
                    acc[p] = fma2(x2, w1a[i8 * 8 + p], acc[p]);
            }
            __half2 hp[8];
#pragma unroll
            for (int p = 0; p < 8; p++) {
                float a, b;
                unpack2(acc[p], a, b);
                hp[p] = __floats2half2_rn(a, (p < 7) ? b : 0.f);
            }
            uint4 q0, q1;
            q0.x = *(unsigned*)&hp[0]; q0.y = *(unsigned*)&hp[1];
            q0.z = *(unsigned*)&hp[2]; q0.w = *(unsigned*)&hp[3];
            q1.x = *(unsigned*)&hp[4]; q1.y = *(unsigned*)&hp[5];
            q1.z = *(unsigned*)&hp[6]; q1.w = *(unsigned*)&hp[7];
            g_pre1h[i * 2]     = q0;
            g_pre1h[i * 2 + 1] = q1;
            g_sa[i] = make_int2(src[e], __float_as_int(avals[e]));
            int prev = __shfl_up_sync(FULLM, r, 1);
            bool head = (lane == 0) || (r != prev);
            unsigned hm = __ballot_sync(FULLM, head);
            unsigned below = hm & (FULLM >> (31 - lane));
            int segoff = lane - (31 - __clz(below));
            bool tail = (lane == 31) || ((hm >> (lane + 1)) & 1u);
            g_rowp[i] = r | (segoff << 18) | (tail ? (1 << 23) : 0);
        }
    }
}

// ===== persistent main kernel =====
__global__ __launch_bounds__(NTHR, 1)
void gnn_main_k(const float* __restrict__ st0,
                const float* __restrict__ old0,
                float* __restrict__ out, int write_num) {
    const int tid = threadIdx.x;
    const int bid = blockIdx.x;
    const int lane = tid & 31;
    const int gw = bid * 32 + (tid >> 5);

    const int myNode = bid * NODE_CHUNK + tid;
    const bool owner = (tid < NODE_CHUNK) && (myNode < N_NODES);
    float s[5], o[5];
    {
        int f = 0;
        if (owner) {
            float ss = 0.f;
#pragma unroll
            for (int i = 0; i < 5; i++) {
                s[i] = st0[myNode * 5 + i];
                o[i] = old0[myNode * 5 + i];
                float d = s[i] - o[i];
                ss += d * d;
            }
            __half2 p01 = __floats2half2_rn(s[0], s[1]);
            __half2 p23 = __floats2half2_rn(s[2], s[3]);
            __half2 p4  = __floats2half2_rn(s[4], 0.f);
            uint4 sv;
            sv.x = *(unsigned*)&p01; sv.y = *(unsigned*)&p23;
            sv.z = *(unsigned*)&p4;  sv.w = 0u;
            __stcg(&g_stateh[myNode], sv);
            __stcg(&g_acc4[myNode * 2], make_float4(0.f, 0.f, 0.f, 0.f));
            __stcg(((float*)&g_acc4[myNode * 2]) + 4, 0.f);
            if (sqrtf(ss + 1e-11f) > THRESH) f = 1;
        }
        int anyf = __syncthreads_or(f);
        if (tid == 0 && anyf) atomicOr(&g_flag_arr[0], 1);
    }
    gsync();

    const ull* w1s = (const ull*)cw.W1s;
    const ull* w2u = (const ull*)cw.W2u;

    int k = 0;
    for (int it = 0; it < MAX_ITER; ++it) {
        if (__ldcg(&g_flag_arr[it]) == 0) break;
        k++;

        // ===== edge phase: software-pipelined =====
        int g = gw;
        int2 sa = make_int2(0, 0);
        int rp = 0;
        uint4 sv = make_uint4(0, 0, 0, 0);
        uint4 pr0 = make_uint4(0, 0, 0, 0);
        uint4 pr1 = make_uint4(0, 0, 0, 0);
        if (g < NGROUPS) {
            int e = g * 32 + lane;
            sa = __ldg(&g_sa[e]);
            rp = __ldg(&g_rowp[e]);
            pr0 = __ldg(&g_pre1h[e * 2]);
            pr1 = __ldg(&g_pre1h[e * 2 + 1]);
            sv = __ldcg(&g_stateh[sa.x]);
        }
        while (g < NGROUPS) {
            int gn = g + NWARPS;

            uint4 cp0 = pr0, cp1 = pr1;
            uint4 csv = sv;
            int crp = rp;
            float cav = __int_as_float(sa.y);
            if (gn < NGROUPS) {
                int en = gn * 32 + lane;
                sa = __ldg(&g_sa[en]);
                rp = __ldg(&g_rowp[en]);
                pr0 = __ldg(&g_pre1h[en * 2]);
                pr1 = __ldg(&g_pre1h[en * 2 + 1]);
                sv = __ldcg(&g_stateh[sa.x]);
            }

            float2 p01 = __half22float2(*(__half2*)&csv.x);
            float2 p23 = __half22float2(*(__half2*)&csv.y);
            float2 p4  = __half22float2(*(__half2*)&csv.z);
            float sx[5] = {p01.x, p01.y, p23.x, p23.y, p4.x};

            // layer 1: acc = pre1 (C-scaled) + state @ C*W1[8:13]
            const __half2* ph0 = (const __half2*)&cp0;
            const __half2* ph1 = (const __half2*)&cp1;
            ull acc[8];
#pragma unroll
            for (int p = 0; p < 4; p++) {
                float2 f = __half22float2(ph0[p]);
                acc[p] = pack2f(f.x, f.y);
            }
#pragma unroll
            for (int p = 0; p < 4; p++) {
                float2 f = __half22float2(ph1[p]);
                acc[4 + p] = pack2f(f.x, f.y);
            }
#pragma unroll
            for (int i = 0; i < 5; i++) {
                ull x2 = pack2(sx[i]);
#pragma unroll
                for (int p = 0; p < 8; p++)
                    acc[p] = fma2(x2, w1s[i * 8 + p], acc[p]);
            }

            // fused tanh->r + layer 2 (folded -2C*W2, B2f)
            ull z[5];
#pragma unroll
            for (int kk = 0; kk < 5; kk++) z[kk] = pack2f(cw.B2f[kk], 0.f);
#pragma unroll
            for (int p = 0; p < 8; p++) {
                float a, b;
                unpack2(acc[p], a, b);
                float ra = rtanh(a);
                float rb = rtanh(b);   // p==7 hi padded with 0 weight: harmless
                ull hp = pack2f(ra, rb);
#pragma unroll
                for (int kk = 0; kk < 5; kk++)
                    z[kk] = fma2(hp, w2u[p * 5 + kk], z[kk]);
            }
            float m2av = -(cav + cav);
            float v0, v1, v2, v3, v4;
            {
                float lo, hi, r;
                unpack2(z[0], lo, hi); r = rtanh(lo + hi); v0 = fmaf(m2av, r, cav);
                unpack2(z[1], lo, hi); r = rtanh(lo + hi); v1 = fmaf(m2av, r, cav);
                unpack2(z[2], lo, hi); r = rtanh(lo + hi); v2 = fmaf(m2av, r, cav);
                unpack2(z[3], lo, hi); r = rtanh(lo + hi); v3 = fmaf(m2av, r, cav);
                unpack2(z[4], lo, hi); r = rtanh(lo + hi); v4 = fmaf(m2av, r, cav);
            }

            // segmented inclusive scan over sorted rows (packed)
            int segoff = (crp >> 18) & 31;
            ull v01 = pack2f(v0, v1);
            ull v23 = pack2f(v2, v3);
#pragma unroll
            for (int d = 1; d < 32; d <<= 1) {
                ull t01 = __shfl_up_sync(FULLM, v01, d);
                ull t23 = __shfl_up_sync(FULLM, v23, d);
                float t4 = __shfl_up_sync(FULLM, v4, d);
                if (segoff >= d) { v01 = add2(v01, t01); v23 = add2(v23, t23); v4 += t4; }
            }
            if (crp & (1 << 23)) {
                int crow = crp & 0x3FFFF;
                float a0, a1, a2, a3;
                unpack2(v01, a0, a1);
                unpack2(v23, a2, a3);
                float* ap = (float*)&g_acc4[crow * 2];
                asm volatile("red.global.add.v4.f32 [%0], {%1,%2,%3,%4};"
                             :: "l"(ap), "f"(a0), "f"(a1), "f"(a2), "f"(a3) : "memory");
                asm volatile("red.global.add.f32 [%0], %1;"
                             :: "l"(ap + 4), "f"(v4) : "memory");
            }
            g = gn;
        }
        gsync();

        // ===== node phase =====
        {
            int f = 0;
            if (owner) {
                float4 a = __ldcg(&g_acc4[myNode * 2]);
                float a4 = __ldcg(((const float*)&g_acc4[myNode * 2]) + 4);
                __stcg(&g_acc4[myNode * 2], make_float4(0.f, 0.f, 0.f, 0.f));
                __stcg(((float*)&g_acc4[myNode * 2]) + 4, 0.f);
                o[0] = s[0]; o[1] = s[1]; o[2] = s[2]; o[3] = s[3]; o[4] = s[4];
                s[0] = a.x; s[1] = a.y; s[2] = a.z; s[3] = a.w; s[4] = a4;
                __half2 p01 = __floats2half2_rn(s[0], s[1]);
                __half2 p23 = __floats2half2_rn(s[2], s[3]);
                __half2 p4  = __floats2half2_rn(s[4], 0.f);
                uint4 svw;
                svw.x = *(unsigned*)&p01; svw.y = *(unsigned*)&p23;
                svw.z = *(unsigned*)&p4;  svw.w = 0u;
                __stcg(&g_stateh[myNode], svw);
                float ss = 0.f;
#pragma unroll
                for (int i = 0; i < 5; i++) { float d = s[i] - o[i]; ss += d * d; }
                if (sqrtf(ss + 1e-11f) > THRESH) f = 1;
            }
            int anyf = __syncthreads_or(f);
            if (tid == 0 && anyf) atomicOr(&g_flag_arr[it + 1], 1);
        }
        gsync();
    }

    // ===== readout (precise) =====
    if (owner) {
        float h[10];
#pragma unroll
        for (int j = 0; j < 10; j++) {
            float a = cw.B3[j];
#pragma unroll
            for (int i = 0; i < 5; i++) a += s[i] * cw.W3[i * 10 + j];
            h[j] = tanhf(a);
        }
        float l[7];
        float m = -1e30f;
#pragma unroll
        for (int c = 0; c < 7; c++) {
            float a = cw.B4[c];
#pragma unroll
            for (int j = 0; j < 10; j++) a += h[j] * cw.W4[j * 7 + c];
            l[c] = a;
            m = fmaxf(m, a);
        }
        float sum = 0.f;
#pragma unroll
        for (int c = 0; c < 7; c++) { float ev = expf(l[c] - m); l[c] = ev; sum += ev; }
        float inv = 1.0f / sum;
#pragma unroll
        for (int c = 0; c < 7; c++) out[(size_t)myNode * 7 + c] = l[c] * inv;
    }
    if (bid == 0 && tid == 0 && write_num) out[(size_t)N_NODES * 7] = (float)k;
}

extern "C" void kernel_launch(void* const* d_in, const int* in_sizes, int n_in,
                              void* d_out, int out_size) {
    const float* edge_feat = (const float*)d_in[0];
    const int*   edge_src  = (const int*)d_in[1];
    const int*   arc_rows  = (const int*)d_in[2];
    const float* arc_vals  = (const float*)d_in[3];
    const float* st0       = (const float*)d_in[4];
    const float* old0      = (const float*)d_in[5];
    const float* W1        = (const float*)d_in[6];
    const float* b1        = (const float*)d_in[7];
    const float* W2        = (const float*)d_in[8];
    const float* b2        = (const float*)d_in[9];
    const float* W3        = (const float*)d_in[10];
    const float* b3        = (const float*)d_in[11];
    const float* W4        = (const float*)d_in[12];
    const float* b4        = (const float*)d_in[13];
    float* out = (float*)d_out;

    build_k<<<NBLK, NTHR>>>(edge_feat, edge_src, arc_rows, arc_vals,
                            W1, b1, W2, b2, W3, b3, W4, b4);

    void *pCW, *pStage;
    cudaGetSymbolAddress(&pCW, cw);
    cudaGetSymbolAddress(&pStage, g_stage);
    cudaMemcpyAsync(pCW, pStage, sizeof(CW), cudaMemcpyDeviceToDevice, 0);

    gnn_main_k<<<NBLK, NTHR>>>(st0, old0, out, (out_size > N_NODES * 7) ? 1 : 0);
}

// round 8
// speedup vs baseline: 2.8833x; 1.2380x over previous
#include <cuda_runtime.h>
#include <cuda_fp16.h>
#include <math.h>

#define N_NODES 100000
#define N_EDGES 1600000
#define MAX_ITER 50
#define THRESH 0.01f
#define CTANH 2.8853900817779268f   // 2*log2(e)

#define NBLK 148
#define NTHR 1024
#define NWARPS (NBLK * 32)                  // 4736
#define NGROUPS (N_EDGES / 32)              // 50000 exact
#define NODE_CHUNK ((N_NODES + NBLK - 1) / NBLK)   // 676
#define FULLM 0xffffffffu

typedef unsigned long long ull;

// all weights in one constant block (single D2D memcpy)
struct CW {
    float2 W1s[40];   // W1 rows 8..12 (UNSCALED), j-paired: [i=5][jp=8]
    float2 W2u[40];   // [p=8][k=5]: (C*W2[2p][k], C*W2[2p+1][k] or 0)
    float  B2c[5];    // C*b2[k]
    float  W3[50], B3[10], W4[70], B4[7];
};
__constant__ CW cw;

// ---- static device scratch ----
__device__ unsigned g_arrive;               // zero-init, monotonic forever
__device__ uint4  g_stateh[N_NODES];        // state as fp16 (5 used of 8)
__device__ float4 g_acc4[N_NODES * 2];      // fp32 accumulator, stride 8
__device__ int    g_flag_arr[MAX_ITER + 2];
__device__ int    g_cnt[N_NODES];
__device__ int    g_cur[N_NODES];
__device__ int    g_part[NBLK];
__device__ int    g_eord[N_EDGES];
__device__ uint4  g_pre1h[N_EDGES * 2];     // (b1 + ef@W1[0:8]) fp16 j-pairs, 32B/edge
__device__ int2   g_sa[N_EDGES];            // {src, av bits}
__device__ int    g_rowp[N_EDGES];          // row | segoff<<18 | tail<<23
__device__ float  g_stage[304];

// single-MUFU tanh (abs err ~5e-4) for the hidden layer
__device__ __forceinline__ float tanha(float x) {
    float r; asm("tanh.approx.f32 %0, %1;" : "=f"(r) : "f"(x)); return r;
}
// accurate path for output layer: r = rcp(1 + 2^z), tanh(x) = 1-2r for z = C*x
__device__ __forceinline__ float rtanh(float z) {
    float ex, r;
    asm("ex2.approx.f32 %0, %1;" : "=f"(ex) : "f"(z));
    float d = ex + 1.0f;
    asm("rcp.approx.f32 %0, %1;" : "=f"(r) : "f"(d));
    return r;
}
__device__ __forceinline__ ull pack2(float x) {
    ull r; asm("mov.b64 %0, {%1, %1};" : "=l"(r) : "f"(x)); return r;
}
__device__ __forceinline__ ull pack2f(float lo, float hi) {
    ull r; asm("mov.b64 %0, {%1, %2};" : "=l"(r) : "f"(lo), "f"(hi)); return r;
}
__device__ __forceinline__ ull fma2(ull a, ull b, ull c) {
    ull r; asm("fma.rn.f32x2 %0, %1, %2, %3;" : "=l"(r) : "l"(a), "l"(b), "l"(c)); return r;
}
__device__ __forceinline__ ull add2(ull a, ull b) {
    ull r; asm("add.rn.f32x2 %0, %1, %2;" : "=l"(r) : "l"(a), "l"(b)); return r;
}
__device__ __forceinline__ void unpack2(ull v, float& lo, float& hi) {
    asm("mov.b64 {%0, %1}, %2;" : "=f"(lo), "=f"(hi) : "l"(v));
}

// grid barrier: release-arrive + acquire-spin (no full MEMBAR)
__device__ __forceinline__ void gsync() {
    __syncthreads();
    if (threadIdx.x == 0) {
        unsigned old;
        asm volatile("atom.add.release.gpu.global.u32 %0, [%1], 1;"
                     : "=r"(old) : "l"(&g_arrive) : "memory");
        unsigned tgt = (old / NBLK + 1u) * NBLK;
        unsigned cur;
        do {
            asm volatile("ld.acquire.gpu.global.u32 %0, [%1];"
                         : "=r"(cur) : "l"(&g_arrive) : "memory");
        } while (cur < tgt);
    }
    __syncthreads();
}

// ===== one persistent build kernel =====
__global__ __launch_bounds__(NTHR, 1)
void build_k(const float* __restrict__ ef, const int* __restrict__ src,
             const int* __restrict__ rows, const float* __restrict__ avals,
             const float* __restrict__ W1, const float* __restrict__ b1,
             const float* __restrict__ W2, const float* __restrict__ b2,
             const float* __restrict__ W3, const float* __restrict__ b3,
             const float* __restrict__ W4, const float* __restrict__ b4) {
    __shared__ int sarr[NTHR];
    __shared__ int spart[NBLK];
    __shared__ float2 sW1a[64];   // W1 rows 0..7 (unscaled), j-paired [i8][jp]
    __shared__ float2 sB1a[8];    // b1 (unscaled) j-paired
    const int tid = threadIdx.x, bid = blockIdx.x;
    const int gsz = NBLK * NTHR;
    const int gi = bid * NTHR + tid;

    // phase 0: zero counters/flags, stage smem W1a/b1, stage constants
    for (int n = gi; n < N_NODES; n += gsz) g_cnt[n] = 0;
    if (gi < MAX_ITER + 2) g_flag_arr[gi] = 0;
    if (tid < 64) {
        int i8 = tid >> 3, jp = tid & 7;
        int j0 = jp * 2, j1 = j0 + 1;
        sW1a[tid] = make_float2(W1[i8 * 15 + j0],
                                (j1 < 15) ? W1[i8 * 15 + j1] : 0.f);
    } else if (tid < 72) {
        int jp = tid - 64;
        int j0 = jp * 2, j1 = j0 + 1;
        sB1a[jp] = make_float2(b1[j0], (j1 < 15) ? b1[j1] : 0.f);
    }
    if (bid == 0) {
        for (int q = tid; q < 40; q += NTHR) {          // W1 rows 8..12 (unscaled)
            int i = 8 + (q >> 3), jp = q & 7;
            int j0 = jp * 2, j1 = j0 + 1;
            g_stage[2 * q]     = W1[i * 15 + j0];
            g_stage[2 * q + 1] = (j1 < 15) ? W1[i * 15 + j1] : 0.f;
        }
        for (int q = tid; q < 40; q += NTHR) {          // C*W2 pairs
            int p = q / 5, kk = q % 5;
            int j0 = 2 * p, j1 = j0 + 1;
            g_stage[80 + 2 * q]     = CTANH * W2[j0 * 5 + kk];
            g_stage[80 + 2 * q + 1] = (j1 < 15) ? CTANH * W2[j1 * 5 + kk] : 0.f;
        }
        if (tid >= 128 && tid < 133) g_stage[160 + tid - 128] = CTANH * b2[tid - 128];
        if (tid >= 160 && tid < 210) g_stage[165 + tid - 160] = W3[tid - 160];
        if (tid >= 224 && tid < 234) g_stage[215 + tid - 224] = b3[tid - 224];
        if (tid >= 256 && tid < 326) g_stage[225 + tid - 256] = W4[tid - 256];
        if (tid >= 352 && tid < 359) g_stage[295 + tid - 352] = b4[tid - 352];
    }
    gsync();

    // phase 1: histogram of rows
    for (int e = gi; e < N_EDGES; e += gsz) atomicAdd(&g_cnt[rows[e]], 1);
    gsync();

    // phase 2: per-block chunk scan
    const int nn = bid * NODE_CHUNK + tid;
    int cv = (tid < NODE_CHUNK && nn < N_NODES) ? g_cnt[nn] : 0;
    sarr[tid] = cv;
    __syncthreads();
    for (int d = 1; d < NTHR; d <<= 1) {
        int v = (tid >= d) ? sarr[tid - d] : 0;
        __syncthreads();
        sarr[tid] += v;
        __syncthreads();
    }
    if (tid == NTHR - 1) g_part[bid] = sarr[NTHR - 1];
    gsync();

    // phase 3: block 0 scans partials
    if (bid == 0) {
        if (tid < NBLK) spart[tid] = g_part[tid];
        __syncthreads();
        if (tid == 0) {
            int run = 0;
            for (int i = 0; i < NBLK; i++) { int t = spart[i]; spart[i] = run; run += t; }
        }
        __syncthreads();
        if (tid < NBLK) g_part[tid] = spart[tid];
    }
    gsync();

    // phase 4: exclusive cursors
    {
        int off = g_part[bid];
        if (tid < NODE_CHUNK && nn < N_NODES) g_cur[nn] = off + sarr[tid] - cv;
    }
    gsync();

    // phase 5: scatter edge order
    for (int e = gi; e < N_EDGES; e += gsz) {
        int p = atomicAdd(&g_cur[rows[e]], 1);
        g_eord[p] = e;
    }
    gsync();

    // phase 6: permute + pre1 compute (fp16 pairs, 2x uint4) + segment metadata
    {
        const int lane = tid & 31;
        const int gw = bid * 32 + (tid >> 5);
        const float4* ef4 = (const float4*)ef;
        const ull* w1a = (const ull*)sW1a;
        const ull* b1a = (const ull*)sB1a;
        for (int g = gw; g < NGROUPS; g += NWARPS) {
            int i = g * 32 + lane;
            int e = g_eord[i];
            int r = rows[e];
            float4 f0 = ef4[e * 2];
            float4 f1 = ef4[e * 2 + 1];
            float in8[8] = {f0.x, f0.y, f0.z, f0.w, f1.x, f1.y, f1.z, f1.w};
            ull acc[8];
#pragma unroll
            for (int p = 0; p < 8; p++) acc[p] = b1a[p];
#pragma unroll
            for (int i8 = 0; i8 < 8; i8++) {
                ull x2 = pack2(in8[i8]);
#pragma unroll
                for (int p = 0; p < 8; p++)
                    acc[p] = fma2(x2, w1a[i8 * 8 + p], acc[p]);
            }
            __half2 hp[8];
#pragma unroll
            for (int p = 0; p < 8; p++) {
                float a, b;
                unpack2(acc[p], a, b);
                hp[p] = __floats2half2_rn(a, (p < 7) ? b : 0.f);
            }
            uint4 q0, q1;
            q0.x = *(unsigned*)&hp[0]; q0.y = *(unsigned*)&hp[1];
            q0.z = *(unsigned*)&hp[2]; q0.w = *(unsigned*)&hp[3];
            q1.x = *(unsigned*)&hp[4]; q1.y = *(unsigned*)&hp[5];
            q1.z = *(unsigned*)&hp[6]; q1.w = *(unsigned*)&hp[7];
            g_pre1h[i * 2]     = q0;
            g_pre1h[i * 2 + 1] = q1;
            g_sa[i] = make_int2(src[e], __float_as_int(avals[e]));
            int prev = __shfl_up_sync(FULLM, r, 1);
            bool head = (lane == 0) || (r != prev);
            unsigned hm = __ballot_sync(FULLM, head);
            unsigned below = hm & (FULLM >> (31 - lane));
            int segoff = lane - (31 - __clz(below));
            bool tail = (lane == 31) || ((hm >> (lane + 1)) & 1u);
            g_rowp[i] = r | (segoff << 18) | (tail ? (1 << 23) : 0);
        }
    }
}

// ===== persistent main kernel =====
__global__ __launch_bounds__(NTHR, 1)
void gnn_main_k(const float* __restrict__ st0,
                const float* __restrict__ old0,
                float* __restrict__ out, int write_num) {
    const int tid = threadIdx.x;
    const int bid = blockIdx.x;
    const int lane = tid & 31;
    const int gw = bid * 32 + (tid >> 5);

    const int myNode = bid * NODE_CHUNK + tid;
    const bool owner = (tid < NODE_CHUNK) && (myNode < N_NODES);
    float s[5], o[5];
    {
        int f = 0;
        if (owner) {
            float ss = 0.f;
#pragma unroll
            for (int i = 0; i < 5; i++) {
                s[i] = st0[myNode * 5 + i];
                o[i] = old0[myNode * 5 + i];
                float d = s[i] - o[i];
                ss += d * d;
            }
            __half2 p01 = __floats2half2_rn(s[0], s[1]);
            __half2 p23 = __floats2half2_rn(s[2], s[3]);
            __half2 p4  = __floats2half2_rn(s[4], 0.f);
            uint4 sv;
            sv.x = *(unsigned*)&p01; sv.y = *(unsigned*)&p23;
            sv.z = *(unsigned*)&p4;  sv.w = 0u;
            __stcg(&g_stateh[myNode], sv);
            __stcg(&g_acc4[myNode * 2], make_float4(0.f, 0.f, 0.f, 0.f));
            __stcg(((float*)&g_acc4[myNode * 2]) + 4, 0.f);
            if (sqrtf(ss + 1e-11f) > THRESH) f = 1;
        }
        int anyf = __syncthreads_or(f);
        if (tid == 0 && anyf) atomicOr(&g_flag_arr[0], 1);
    }
    gsync();

    const ull* w1s = (const ull*)cw.W1s;
    const ull* w2u = (const ull*)cw.W2u;

    int k = 0;
    for (int it = 0; it < MAX_ITER; ++it) {
        if (__ldcg(&g_flag_arr[it]) == 0) break;
        k++;

        // ===== edge phase: software-pipelined =====
        int g = gw;
        int2 sa = make_int2(0, 0);
        int rp = 0;
        uint4 sv = make_uint4(0, 0, 0, 0);
        uint4 pr0 = make_uint4(0, 0, 0, 0);
        uint4 pr1 = make_uint4(0, 0, 0, 0);
        if (g < NGROUPS) {
            int e = g * 32 + lane;
            sa = __ldg(&g_sa[e]);
            rp = __ldg(&g_rowp[e]);
            pr0 = __ldg(&g_pre1h[e * 2]);
            pr1 = __ldg(&g_pre1h[e * 2 + 1]);
            sv = __ldcg(&g_stateh[sa.x]);
        }
        while (g < NGROUPS) {
            int gn = g + NWARPS;

            uint4 cp0 = pr0, cp1 = pr1;
            uint4 csv = sv;
            int crp = rp;
            float cav = __int_as_float(sa.y);
            if (gn < NGROUPS) {
                int en = gn * 32 + lane;
                sa = __ldg(&g_sa[en]);
                rp = __ldg(&g_rowp[en]);
                pr0 = __ldg(&g_pre1h[en * 2]);
                pr1 = __ldg(&g_pre1h[en * 2 + 1]);
                sv = __ldcg(&g_stateh[sa.x]);
            }

            float2 p01 = __half22float2(*(__half2*)&csv.x);
            float2 p23 = __half22float2(*(__half2*)&csv.y);
            float2 p4  = __half22float2(*(__half2*)&csv.z);
            float sx[5] = {p01.x, p01.y, p23.x, p23.y, p4.x};

            // layer 1: acc = pre1 + state @ W1[8:13]  (unscaled)
            const __half2* ph0 = (const __half2*)&cp0;
            const __half2* ph1 = (const __half2*)&cp1;
            ull acc[8];
#pragma unroll
            for (int p = 0; p < 4; p++) {
                float2 f = __half22float2(ph0[p]);
                acc[p] = pack2f(f.x, f.y);
            }
#pragma unroll
            for (int p = 0; p < 4; p++) {
                float2 f = __half22float2(ph1[p]);
                acc[4 + p] = pack2f(f.x, f.y);
            }
#pragma unroll
            for (int i = 0; i < 5; i++) {
                ull x2 = pack2(sx[i]);
#pragma unroll
                for (int p = 0; p < 8; p++)
                    acc[p] = fma2(x2, w1s[i * 8 + p], acc[p]);
            }

            // layer 1 tanh (single-MUFU approx) + layer 2 accumulate (C-scaled)
            ull z[5];
#pragma unroll
            for (int kk = 0; kk < 5; kk++) z[kk] = pack2f(cw.B2c[kk], 0.f);
#pragma unroll
            for (int p = 0; p < 8; p++) {
                float a, b;
                unpack2(acc[p], a, b);
                float ta = tanha(a);
                float tb = tanha(b);   // p==7 hi is 0 -> tanh(0)=0, weight 0: harmless
                ull hp = pack2f(ta, tb);
#pragma unroll
                for (int kk = 0; kk < 5; kk++)
                    z[kk] = fma2(hp, w2u[p * 5 + kk], z[kk]);
            }
            // layer 2 tanh: accurate two-MUFU path (z is C-scaled)
            float m2av = -(cav + cav);
            float v0, v1, v2, v3, v4;
            {
                float lo, hi, r;
                unpack2(z[0], lo, hi); r = rtanh(lo + hi); v0 = fmaf(m2av, r, cav);
                unpack2(z[1], lo, hi); r = rtanh(lo + hi); v1 = fmaf(m2av, r, cav);
                unpack2(z[2], lo, hi); r = rtanh(lo + hi); v2 = fmaf(m2av, r, cav);
                unpack2(z[3], lo, hi); r = rtanh(lo + hi); v3 = fmaf(m2av, r, cav);
                unpack2(z[4], lo, hi); r = rtanh(lo + hi); v4 = fmaf(m2av, r, cav);
            }

            // segmented inclusive scan over sorted rows (packed)
            int segoff = (crp >> 18) & 31;
            ull v01 = pack2f(v0, v1);
            ull v23 = pack2f(v2, v3);
#pragma unroll
            for (int d = 1; d < 32; d <<= 1) {
                ull t01 = __shfl_up_sync(FULLM, v01, d);
                ull t23 = __shfl_up_sync(FULLM, v23, d);
                float t4 = __shfl_up_sync(FULLM, v4, d);
                if (segoff >= d) { v01 = add2(v01, t01); v23 = add2(v23, t23); v4 += t4; }
            }
            if (crp & (1 << 23)) {
                int crow = crp & 0x3FFFF;
                float a0, a1, a2, a3;
                unpack2(v01, a0, a1);
                unpack2(v23, a2, a3);
                float* ap = (float*)&g_acc4[crow * 2];
                asm volatile("red.global.add.v4.f32 [%0], {%1,%2,%3,%4};"
                             :: "l"(ap), "f"(a0), "f"(a1), "f"(a2), "f"(a3) : "memory");
                asm volatile("red.global.add.f32 [%0], %1;"
                             :: "l"(ap + 4), "f"(v4) : "memory");
            }
            g = gn;
        }
        gsync();

        // ===== node phase =====
        {
            int f = 0;
            if (owner) {
                float4 a = __ldcg(&g_acc4[myNode * 2]);
                float a4 = __ldcg(((const float*)&g_acc4[myNode * 2]) + 4);
                __stcg(&g_acc4[myNode * 2], make_float4(0.f, 0.f, 0.f, 0.f));
                __stcg(((float*)&g_acc4[myNode * 2]) + 4, 0.f);
                o[0] = s[0]; o[1] = s[1]; o[2] = s[2]; o[3] = s[3]; o[4] = s[4];
                s[0] = a.x; s[1] = a.y; s[2] = a.z; s[3] = a.w; s[4] = a4;
                __half2 p01 = __floats2half2_rn(s[0], s[1]);
                __half2 p23 = __floats2half2_rn(s[2], s[3]);
                __half2 p4  = __floats2half2_rn(s[4], 0.f);
                uint4 svw;
                svw.x = *(unsigned*)&p01; svw.y = *(unsigned*)&p23;
                svw.z = *(unsigned*)&p4;  svw.w = 0u;
                __stcg(&g_stateh[myNode], svw);
                float ss = 0.f;
#pragma unroll
                for (int i = 0; i < 5; i++) { float d = s[i] - o[i]; ss += d * d; }
                if (sqrtf(ss + 1e-11f) > THRESH) f = 1;
            }
            int anyf = __syncthreads_or(f);
            if (tid == 0 && anyf) atomicOr(&g_flag_arr[it + 1], 1);
        }
        gsync();
    }

    // ===== readout (precise) =====
    if (owner) {
        float h[10];
#pragma unroll
        for (int j = 0; j < 10; j++) {
            float a = cw.B3[j];
#pragma unroll
            for (int i = 0; i < 5; i++) a += s[i] * cw.W3[i * 10 + j];
            h[j] = tanhf(a);
        }
        float l[7];
        float m = -1e30f;
#pragma unroll
        for (int c = 0; c < 7; c++) {
            float a = cw.B4[c];
#pragma unroll
            for (int j = 0; j < 10; j++) a += h[j] * cw.W4[j * 7 + c];
            l[c] = a;
            m = fmaxf(m, a);
        }
        float sum = 0.f;
#pragma unroll
        for (int c = 0; c < 7; c++) { float ev = expf(l[c] - m); l[c] = ev; sum += ev; }
        float inv = 1.0f / sum;
#pragma unroll
        for (int c = 0; c < 7; c++) out[(size_t)myNode * 7 + c] = l[c] * inv;
    }
    if (bid == 0 && tid == 0 && write_num) out[(size_t)N_NODES * 7] = (float)k;
}

extern "C" void kernel_launch(void* const* d_in, const int* in_sizes, int n_in,
                              void* d_out, int out_size) {
    const float* edge_feat = (const float*)d_in[0];
    const int*   edge_src  = (const int*)d_in[1];
    const int*   arc_rows  = (const int*)d_in[2];
    const float* arc_vals  = (const float*)d_in[3];
    const float* st0       = (const float*)d_in[4];
    const float* old0      = (const float*)d_in[5];
    const float* W1        = (const float*)d_in[6];
    const float* b1        = (const float*)d_in[7];
    const float* W2        = (const float*)d_in[8];
    const float* b2        = (const float*)d_in[9];
    const float* W3        = (const float*)d_in[10];
    const float* b3        = (const float*)d_in[11];
    const float* W4        = (const float*)d_in[12];
    const float* b4        = (const float*)d_in[13];
    float* out = (float*)d_out;

    build_k<<<NBLK, NTHR>>>(edge_feat, edge_src, arc_rows, arc_vals,
                            W1, b1, W2, b2, W3, b3, W4, b4);

    void *pCW, *pStage;
    cudaGetSymbolAddress(&pCW, cw);
    cudaGetSymbolAddress(&pStage, g_stage);
    cudaMemcpyAsync(pCW, pStage, sizeof(CW), cudaMemcpyDeviceToDevice, 0);

    gnn_main_k<<<NBLK, NTHR>>>(st0, old0, out, (out_size > N_NODES * 7) ? 1 : 0);
}